// round 2
// baseline (speedup 1.0000x reference)
#include <cuda_runtime.h>
#include <math.h>

// Problem constants
// x: [16, 64, 64, 512] -> rows M = 65536, C = 512
// theta: [M, 64], phi/g pooled to [16*1024, 64/256], tmp: [M, 256], out: [M, 512]
#define M_ROWS 65536
#define C_IN   512
#define D_DIM  64
#define V_DIM  256
#define BATCH  16
#define SEQ_Q  4096
#define SEQ_K  1024

// ---------------- scratch (device globals; no allocation allowed) ----------------
__device__ float g_theta [M_ROWS * D_DIM];        // 16 MB
__device__ float g_phiraw[M_ROWS * D_DIM];        // 16 MB
__device__ float g_graw  [M_ROWS * V_DIM];        // 64 MB
__device__ float g_phiP  [BATCH * SEQ_K * D_DIM]; //  4 MB
__device__ float g_gP    [BATCH * SEQ_K * V_DIM]; // 16 MB
__device__ float g_tmp   [M_ROWS * V_DIM];        // 64 MB

// ---------------- generic fp32 GEMM: C[M,N] = A[M,K] @ B[K,N] ----------------
// BM=64, BN=64, BK=16, 256 threads, 4x4 microtile per thread.
// Optional epilogue: C = gamma * acc + res (residual add for final projection).
__global__ __launch_bounds__(256) void gemm_k(
    const float* __restrict__ A, const float* __restrict__ B, float* __restrict__ C,
    int M, int N, int K,
    const float* __restrict__ res, const float* __restrict__ gammaP)
{
    __shared__ float As[16][68];  // transposed: As[k][m]
    __shared__ float Bs[16][68];  // Bs[k][n]

    const int tid = threadIdx.x;
    const int tx = tid & 15;       // n-group
    const int ty = tid >> 4;       // m-group
    const int m0 = blockIdx.y * 64;
    const int n0 = blockIdx.x * 64;

    const int arow = tid >> 2, akq = tid & 3;   // A loader: 64 rows x 4 k-quads
    const int brow = tid >> 4, bnq = tid & 15;  // B loader: 16 rows x 16 n-quads

    const float* Aptr = A + (size_t)(m0 + arow) * K + akq * 4;
    const float* Bptr = B + (size_t)brow * N + n0 + bnq * 4;

    float acc[4][4];
    #pragma unroll
    for (int i = 0; i < 4; i++)
        #pragma unroll
        for (int j = 0; j < 4; j++) acc[i][j] = 0.f;

    for (int k0 = 0; k0 < K; k0 += 16) {
        float4 av = *(const float4*)(Aptr + k0);
        float4 bv = *(const float4*)(Bptr + (size_t)k0 * N);
        __syncthreads();   // previous tile's compute done before overwrite
        As[akq * 4 + 0][arow] = av.x;
        As[akq * 4 + 1][arow] = av.y;
        As[akq * 4 + 2][arow] = av.z;
        As[akq * 4 + 3][arow] = av.w;
        *(float4*)&Bs[brow][bnq * 4] = bv;
        __syncthreads();
        #pragma unroll
        for (int kk = 0; kk < 16; kk++) {
            float4 a4 = *(const float4*)&As[kk][ty * 4];
            float4 b4 = *(const float4*)&Bs[kk][tx * 4];
            float a[4] = {a4.x, a4.y, a4.z, a4.w};
            float b[4] = {b4.x, b4.y, b4.z, b4.w};
            #pragma unroll
            for (int i = 0; i < 4; i++)
                #pragma unroll
                for (int j = 0; j < 4; j++)
                    acc[i][j] = fmaf(a[i], b[j], acc[i][j]);
        }
    }

    if (res) {
        const float gamma = *gammaP;
        #pragma unroll
        for (int i = 0; i < 4; i++) {
            int row = m0 + ty * 4 + i;
            size_t off = (size_t)row * N + n0 + tx * 4;
            float4 xr = *(const float4*)(res + off);
            float4 o;
            o.x = fmaf(gamma, acc[i][0], xr.x);
            o.y = fmaf(gamma, acc[i][1], xr.y);
            o.z = fmaf(gamma, acc[i][2], xr.z);
            o.w = fmaf(gamma, acc[i][3], xr.w);
            *(float4*)(C + off) = o;
        }
    } else {
        #pragma unroll
        for (int i = 0; i < 4; i++) {
            int row = m0 + ty * 4 + i;
            size_t off = (size_t)row * N + n0 + tx * 4;
            *(float4*)(C + off) = make_float4(acc[i][0], acc[i][1], acc[i][2], acc[i][3]);
        }
    }
}

// ---------------- 2x2 maxpool: phiraw/graw -> phiP/gP ----------------
__global__ void pool_k(const float* __restrict__ phiraw, const float* __restrict__ graw,
                       float* __restrict__ phiP, float* __restrict__ gP)
{
    const int NPHI4 = BATCH * SEQ_K * (D_DIM / 4);  // 262144
    const int NG4   = BATCH * SEQ_K * (V_DIM / 4);  // 1048576
    int i = blockIdx.x * blockDim.x + threadIdx.x;
    if (i < NPHI4) {
        int bp = i >> 4, c4 = i & 15;
        int b = bp >> 10, ij = bp & 1023, ii = ij >> 5, jj = ij & 31;
        int r = b * 4096 + ii * 128 + jj * 2;   // row = ((b*64 + 2i)*64 + 2j)
        float4 v0 = *((const float4*)(phiraw + (size_t)r * 64) + c4);
        float4 v1 = *((const float4*)(phiraw + (size_t)(r + 1) * 64) + c4);
        float4 v2 = *((const float4*)(phiraw + (size_t)(r + 64) * 64) + c4);
        float4 v3 = *((const float4*)(phiraw + (size_t)(r + 65) * 64) + c4);
        float4 o;
        o.x = fmaxf(fmaxf(v0.x, v1.x), fmaxf(v2.x, v3.x));
        o.y = fmaxf(fmaxf(v0.y, v1.y), fmaxf(v2.y, v3.y));
        o.z = fmaxf(fmaxf(v0.z, v1.z), fmaxf(v2.z, v3.z));
        o.w = fmaxf(fmaxf(v0.w, v1.w), fmaxf(v2.w, v3.w));
        *((float4*)(phiP + (size_t)bp * 64) + c4) = o;
    } else {
        int j = i - NPHI4;
        if (j < NG4) {
            int bp = j >> 6, c4 = j & 63;
            int b = bp >> 10, ij = bp & 1023, ii = ij >> 5, jj = ij & 31;
            int r = b * 4096 + ii * 128 + jj * 2;
            float4 v0 = *((const float4*)(graw + (size_t)r * 256) + c4);
            float4 v1 = *((const float4*)(graw + (size_t)(r + 1) * 256) + c4);
            float4 v2 = *((const float4*)(graw + (size_t)(r + 64) * 256) + c4);
            float4 v3 = *((const float4*)(graw + (size_t)(r + 65) * 256) + c4);
            float4 o;
            o.x = fmaxf(fmaxf(v0.x, v1.x), fmaxf(v2.x, v3.x));
            o.y = fmaxf(fmaxf(v0.y, v1.y), fmaxf(v2.y, v3.y));
            o.z = fmaxf(fmaxf(v0.z, v1.z), fmaxf(v2.z, v3.z));
            o.w = fmaxf(fmaxf(v0.w, v1.w), fmaxf(v2.w, v3.w));
            *((float4*)(gP + (size_t)bp * 256) + c4) = o;
        }
    }
}

// ---------------- flash attention: tmp = softmax(theta @ phi^T) @ g ----------------
// Block = 64 queries of one batch; loop over 16 key tiles of 64 keys each.
// 256 threads: (ty,tx) 16x16. ty owns 4 queries; tx owns 4 keys (scores) / 16 v-cols (PV).
__global__ __launch_bounds__(256) void attn_k(
    const float* __restrict__ theta, const float* __restrict__ phiP,
    const float* __restrict__ gP, float* __restrict__ tmp)
{
    extern __shared__ float sm[];
    float* thT = sm;                 // [d=64][68] transposed theta tile
    float* phT = sm + 64 * 68;       // [d=64][68] transposed phi tile
    float* ps  = sm + 2 * 64 * 68;   // [q=64][68] exp'd probabilities
    float* gs  = sm + 3 * 64 * 68;   // [k=64][256] g tile

    const int tid = threadIdx.x;
    const int tx = tid & 15;
    const int ty = tid >> 4;
    const int b  = blockIdx.y;
    const int qt = blockIdx.x;
    const int qbase = b * SEQ_Q + qt * 64;

    // load theta tile transposed: thT[d][q]
    #pragma unroll
    for (int idx = tid; idx < 64 * 16; idx += 256) {
        int q = idx >> 4, d4 = idx & 15;
        float4 v = *(const float4*)(theta + (size_t)(qbase + q) * 64 + d4 * 4);
        thT[(d4 * 4 + 0) * 68 + q] = v.x;
        thT[(d4 * 4 + 1) * 68 + q] = v.y;
        thT[(d4 * 4 + 2) * 68 + q] = v.z;
        thT[(d4 * 4 + 3) * 68 + q] = v.w;
    }

    float m[4], l[4], acc[4][16];
    #pragma unroll
    for (int i = 0; i < 4; i++) {
        m[i] = -1e30f; l[i] = 0.f;
        #pragma unroll
        for (int v = 0; v < 16; v++) acc[i][v] = 0.f;
    }

    for (int kt = 0; kt < 16; kt++) {
        __syncthreads();   // previous PV reads complete (also covers theta stores, iter 0)
        const int kbase = b * SEQ_K + kt * 64;
        // load phi tile transposed: phT[d][k]
        #pragma unroll
        for (int idx = tid; idx < 64 * 16; idx += 256) {
            int kq = idx >> 4, d4 = idx & 15;
            float4 v = *(const float4*)(phiP + (size_t)(kbase + kq) * 64 + d4 * 4);
            phT[(d4 * 4 + 0) * 68 + kq] = v.x;
            phT[(d4 * 4 + 1) * 68 + kq] = v.y;
            phT[(d4 * 4 + 2) * 68 + kq] = v.z;
            phT[(d4 * 4 + 3) * 68 + kq] = v.w;
        }
        // load g tile: gs[k][v]
        #pragma unroll
        for (int idx = tid; idx < 64 * 64; idx += 256) {
            int kr = idx >> 6, c4 = idx & 63;
            *(float4*)&gs[kr * 256 + c4 * 4] =
                *(const float4*)(gP + (size_t)(kbase + kr) * 256 + c4 * 4);
        }
        __syncthreads();

        // scores S = theta @ phi^T : thread computes s[4 q][4 k]
        float s[4][4];
        #pragma unroll
        for (int i = 0; i < 4; i++)
            #pragma unroll
            for (int j = 0; j < 4; j++) s[i][j] = 0.f;
        #pragma unroll 8
        for (int d = 0; d < 64; d++) {
            float4 a4 = *(const float4*)&thT[d * 68 + ty * 4];
            float4 b4 = *(const float4*)&phT[d * 68 + tx * 4];
            float a[4] = {a4.x, a4.y, a4.z, a4.w};
            float bb[4] = {b4.x, b4.y, b4.z, b4.w};
            #pragma unroll
            for (int i = 0; i < 4; i++)
                #pragma unroll
                for (int j = 0; j < 4; j++)
                    s[i][j] = fmaf(a[i], bb[j], s[i][j]);
        }

        // online softmax: row max across 16 tx lanes (lanes 0-15 / 16-31 per warp)
        float tmax[4];
        #pragma unroll
        for (int i = 0; i < 4; i++) {
            float t = fmaxf(fmaxf(s[i][0], s[i][1]), fmaxf(s[i][2], s[i][3]));
            #pragma unroll
            for (int o = 8; o >= 1; o >>= 1)
                t = fmaxf(t, __shfl_xor_sync(0xffffffffu, t, o));
            tmax[i] = t;
        }
        float p[4][4], rs[4];
        #pragma unroll
        for (int i = 0; i < 4; i++) {
            float mn = fmaxf(m[i], tmax[i]);
            float sc = __expf(m[i] - mn);
            m[i] = mn;
            float r = 0.f;
            #pragma unroll
            for (int j = 0; j < 4; j++) {
                p[i][j] = __expf(s[i][j] - mn);
                r += p[i][j];
            }
            #pragma unroll
            for (int o = 8; o >= 1; o >>= 1)
                r += __shfl_xor_sync(0xffffffffu, r, o);
            rs[i] = r;
            l[i] = l[i] * sc + rs[i];
            #pragma unroll
            for (int v = 0; v < 16; v++) acc[i][v] *= sc;
        }
        // write probabilities to smem
        #pragma unroll
        for (int i = 0; i < 4; i++)
            #pragma unroll
            for (int j = 0; j < 4; j++)
                ps[(ty * 4 + i) * 68 + tx * 4 + j] = p[i][j];
        __syncthreads();

        // PV: acc[q][v] += P[q][k] * g[k][v], v-cols tx*16 .. tx*16+15
        #pragma unroll 2
        for (int k = 0; k < 64; k++) {
            float pk[4];
            #pragma unroll
            for (int i = 0; i < 4; i++) pk[i] = ps[(ty * 4 + i) * 68 + k];
            #pragma unroll
            for (int v4 = 0; v4 < 4; v4++) {
                float4 gv = *(const float4*)&gs[k * 256 + tx * 16 + v4 * 4];
                #pragma unroll
                for (int i = 0; i < 4; i++) {
                    acc[i][v4 * 4 + 0] = fmaf(pk[i], gv.x, acc[i][v4 * 4 + 0]);
                    acc[i][v4 * 4 + 1] = fmaf(pk[i], gv.y, acc[i][v4 * 4 + 1]);
                    acc[i][v4 * 4 + 2] = fmaf(pk[i], gv.z, acc[i][v4 * 4 + 2]);
                    acc[i][v4 * 4 + 3] = fmaf(pk[i], gv.w, acc[i][v4 * 4 + 3]);
                }
            }
        }
    }

    // normalize and write tmp[q][v]
    #pragma unroll
    for (int i = 0; i < 4; i++) {
        float inv = 1.f / l[i];
        size_t row = (size_t)(qbase + ty * 4 + i) * 256 + tx * 16;
        #pragma unroll
        for (int v4 = 0; v4 < 4; v4++) {
            float4 o = make_float4(acc[i][v4 * 4 + 0] * inv, acc[i][v4 * 4 + 1] * inv,
                                   acc[i][v4 * 4 + 2] * inv, acc[i][v4 * 4 + 3] * inv);
            *(float4*)(tmp + row + v4 * 4) = o;
        }
    }
}

// ---------------- launch ----------------
extern "C" void kernel_launch(void* const* d_in, const int* in_sizes, int n_in,
                              void* d_out, int out_size)
{
    const float* x     = (const float*)d_in[0];
    const float* Wt    = (const float*)d_in[1];
    const float* Wp    = (const float*)d_in[2];
    const float* Wg    = (const float*)d_in[3];
    const float* Wo    = (const float*)d_in[4];
    const float* gamma = (const float*)d_in[5];
    float* out = (float*)d_out;

    float *theta, *phiraw, *graw, *phiP, *gP, *tmp;
    cudaGetSymbolAddress((void**)&theta,  g_theta);
    cudaGetSymbolAddress((void**)&phiraw, g_phiraw);
    cudaGetSymbolAddress((void**)&graw,   g_graw);
    cudaGetSymbolAddress((void**)&phiP,   g_phiP);
    cudaGetSymbolAddress((void**)&gP,     g_gP);
    cudaGetSymbolAddress((void**)&tmp,    g_tmp);

    const int ATTN_SMEM = (3 * 64 * 68 + 64 * 256) * 4;  // 117760 B
    cudaFuncSetAttribute(attn_k, cudaFuncAttributeMaxDynamicSharedMemorySize, ATTN_SMEM);

    dim3 blk(256);
    // projections
    gemm_k<<<dim3(1, M_ROWS / 64), blk>>>(x, Wt, theta,  M_ROWS, D_DIM, C_IN, nullptr, nullptr);
    gemm_k<<<dim3(1, M_ROWS / 64), blk>>>(x, Wp, phiraw, M_ROWS, D_DIM, C_IN, nullptr, nullptr);
    gemm_k<<<dim3(4, M_ROWS / 64), blk>>>(x, Wg, graw,   M_ROWS, V_DIM, C_IN, nullptr, nullptr);
    // 2x2 maxpool
    {
        int total = BATCH * SEQ_K * (D_DIM / 4) + BATCH * SEQ_K * (V_DIM / 4);
        pool_k<<<(total + 255) / 256, 256>>>(phiraw, graw, phiP, gP);
    }
    // fused softmax attention
    attn_k<<<dim3(SEQ_Q / 64, BATCH), blk, ATTN_SMEM>>>(theta, phiP, gP, tmp);
    // output projection + residual: out = gamma * (tmp @ Wo) + x
    gemm_k<<<dim3(8, M_ROWS / 64), blk>>>(tmp, Wo, out, M_ROWS, C_IN, V_DIM, x, gamma);
}

// round 3
// speedup vs baseline: 1.7103x; 1.7103x over previous
#include <cuda_runtime.h>
#include <math.h>

// x: [16, 64, 64, 512] -> rows M = 65536, C = 512
#define M_ROWS 65536
#define C_IN   512
#define D_DIM  64
#define V_DIM  256
#define BATCH  16
#define SEQ_Q  4096
#define SEQ_K  1024
#define NPROJ  384   // 64 theta | 64 phi | 256 g

// ---------------- scratch (device globals; no allocation allowed) ----------------
__device__ float g_proj[M_ROWS * NPROJ];          // 96 MB: [theta|phi|g] per row
__device__ float g_phiP[BATCH * SEQ_K * D_DIM];   //  4 MB
__device__ float g_gP  [BATCH * SEQ_K * V_DIM];   // 16 MB
__device__ float g_tmp [M_ROWS * V_DIM];          // 64 MB
__device__ float g_Wcat[C_IN * NPROJ];            // 0.75 MB packed weights

// ---------------- pack [W_theta | W_phi | W_g] -> Wcat[512,384] ----------------
__global__ void pack_k(const float* __restrict__ Wt, const float* __restrict__ Wp,
                       const float* __restrict__ Wg, float* __restrict__ Wcat)
{
    int i = blockIdx.x * blockDim.x + threadIdx.x;   // over 512*384
    if (i >= C_IN * NPROJ) return;
    int r = i / NPROJ, c = i % NPROJ;
    float v;
    if (c < 64)       v = Wt[r * 64 + c];
    else if (c < 128) v = Wp[r * 64 + (c - 64)];
    else              v = Wg[r * 256 + (c - 128)];
    Wcat[i] = v;
}

// ---------------- fp32 GEMM: C[M,N] = A[M,K] @ B[K,N] ----------------
// BM=BN=128, BK=16, 256 threads, 8x8 microtile, double-buffered smem.
// Optional epilogue: C = gamma * acc + res.
__global__ __launch_bounds__(256, 2) void gemm128(
    const float* __restrict__ A, const float* __restrict__ B, float* __restrict__ C,
    int M, int N, int K,
    const float* __restrict__ res, const float* __restrict__ gammaP)
{
    __shared__ float As[2][16][132];   // As[buf][k][m]
    __shared__ float Bs[2][16][132];   // Bs[buf][k][n]

    const int tid = threadIdx.x;
    const int tx = tid & 15;           // n-group
    const int ty = tid >> 4;           // m-group
    const int m0 = blockIdx.y * 128;
    const int n0 = blockIdx.x * 128;

    const int ar0 = tid >> 2, akq = tid & 3;   // A: rows ar0, ar0+64; k-quad akq
    const int bk0 = tid >> 5, bnq = tid & 31;  // B: k-rows bk0, bk0+8; n-quad bnq

    const float* Ap = A + (size_t)(m0 + ar0) * K + akq * 4;
    const float* Bp = B + (size_t)bk0 * N + n0 + bnq * 4;

    float acc[8][8];
    #pragma unroll
    for (int i = 0; i < 8; i++)
        #pragma unroll
        for (int j = 0; j < 8; j++) acc[i][j] = 0.f;

    // prologue: tile 0
    float4 av0 = *(const float4*)(Ap);
    float4 av1 = *(const float4*)(Ap + (size_t)64 * K);
    float4 bv0 = *(const float4*)(Bp);
    float4 bv1 = *(const float4*)(Bp + (size_t)8 * N);
    As[0][akq * 4 + 0][ar0]      = av0.x;
    As[0][akq * 4 + 1][ar0]      = av0.y;
    As[0][akq * 4 + 2][ar0]      = av0.z;
    As[0][akq * 4 + 3][ar0]      = av0.w;
    As[0][akq * 4 + 0][ar0 + 64] = av1.x;
    As[0][akq * 4 + 1][ar0 + 64] = av1.y;
    As[0][akq * 4 + 2][ar0 + 64] = av1.z;
    As[0][akq * 4 + 3][ar0 + 64] = av1.w;
    *(float4*)&Bs[0][bk0][bnq * 4]     = bv0;
    *(float4*)&Bs[0][bk0 + 8][bnq * 4] = bv1;
    __syncthreads();

    const int NT = K >> 4;
    int cur = 0;
    for (int t = 0; t < NT; ++t) {
        if (t + 1 < NT) {   // prefetch next tile to registers
            const float* Ap2 = Ap + (t + 1) * 16;
            const float* Bp2 = Bp + (size_t)(t + 1) * 16 * N;
            av0 = *(const float4*)(Ap2);
            av1 = *(const float4*)(Ap2 + (size_t)64 * K);
            bv0 = *(const float4*)(Bp2);
            bv1 = *(const float4*)(Bp2 + (size_t)8 * N);
        }
        const float (*Asc)[132] = As[cur];
        const float (*Bsc)[132] = Bs[cur];
        #pragma unroll
        for (int kk = 0; kk < 16; ++kk) {
            float4 a0 = *(const float4*)&Asc[kk][ty * 4];
            float4 a1 = *(const float4*)&Asc[kk][64 + ty * 4];
            float4 b0 = *(const float4*)&Bsc[kk][tx * 4];
            float4 b1 = *(const float4*)&Bsc[kk][64 + tx * 4];
            float ar[8] = {a0.x, a0.y, a0.z, a0.w, a1.x, a1.y, a1.z, a1.w};
            float br[8] = {b0.x, b0.y, b0.z, b0.w, b1.x, b1.y, b1.z, b1.w};
            #pragma unroll
            for (int i = 0; i < 8; i++)
                #pragma unroll
                for (int j = 0; j < 8; j++)
                    acc[i][j] = fmaf(ar[i], br[j], acc[i][j]);
        }
        if (t + 1 < NT) {
            int nxt = cur ^ 1;
            As[nxt][akq * 4 + 0][ar0]      = av0.x;
            As[nxt][akq * 4 + 1][ar0]      = av0.y;
            As[nxt][akq * 4 + 2][ar0]      = av0.z;
            As[nxt][akq * 4 + 3][ar0]      = av0.w;
            As[nxt][akq * 4 + 0][ar0 + 64] = av1.x;
            As[nxt][akq * 4 + 1][ar0 + 64] = av1.y;
            As[nxt][akq * 4 + 2][ar0 + 64] = av1.z;
            As[nxt][akq * 4 + 3][ar0 + 64] = av1.w;
            *(float4*)&Bs[nxt][bk0][bnq * 4]     = bv0;
            *(float4*)&Bs[nxt][bk0 + 8][bnq * 4] = bv1;
            __syncthreads();
            cur = nxt;
        }
    }

    // epilogue
    if (res) {
        const float gamma = *gammaP;
        #pragma unroll
        for (int i = 0; i < 8; i++) {
            int row = m0 + ((i < 4) ? (ty * 4 + i) : (64 + ty * 4 + i - 4));
            size_t off0 = (size_t)row * N + n0 + tx * 4;
            float4 x0 = *(const float4*)(res + off0);
            float4 x1 = *(const float4*)(res + off0 + 64);
            float4 o0, o1;
            o0.x = fmaf(gamma, acc[i][0], x0.x); o0.y = fmaf(gamma, acc[i][1], x0.y);
            o0.z = fmaf(gamma, acc[i][2], x0.z); o0.w = fmaf(gamma, acc[i][3], x0.w);
            o1.x = fmaf(gamma, acc[i][4], x1.x); o1.y = fmaf(gamma, acc[i][5], x1.y);
            o1.z = fmaf(gamma, acc[i][6], x1.z); o1.w = fmaf(gamma, acc[i][7], x1.w);
            *(float4*)(C + off0)      = o0;
            *(float4*)(C + off0 + 64) = o1;
        }
    } else {
        #pragma unroll
        for (int i = 0; i < 8; i++) {
            int row = m0 + ((i < 4) ? (ty * 4 + i) : (64 + ty * 4 + i - 4));
            size_t off0 = (size_t)row * N + n0 + tx * 4;
            *(float4*)(C + off0)      = make_float4(acc[i][0], acc[i][1], acc[i][2], acc[i][3]);
            *(float4*)(C + off0 + 64) = make_float4(acc[i][4], acc[i][5], acc[i][6], acc[i][7]);
        }
    }
}

// ---------------- 2x2 maxpool: proj(phi|g cols) -> phiP/gP ----------------
__global__ void pool_k(const float* __restrict__ proj,
                       float* __restrict__ phiP, float* __restrict__ gP)
{
    const int NPHI4 = BATCH * SEQ_K * (D_DIM / 4);  // 262144
    const int NG4   = BATCH * SEQ_K * (V_DIM / 4);  // 1048576
    int i = blockIdx.x * blockDim.x + threadIdx.x;
    if (i < NPHI4) {
        int bp = i >> 4, c4 = i & 15;
        int b = bp >> 10, ij = bp & 1023, ii = ij >> 5, jj = ij & 31;
        int r = b * 4096 + ii * 128 + jj * 2;
        const float* base = proj + 64 + (size_t)c4 * 4;   // phi cols start at 64
        float4 v0 = *(const float4*)(base + (size_t)r * NPROJ);
        float4 v1 = *(const float4*)(base + (size_t)(r + 1) * NPROJ);
        float4 v2 = *(const float4*)(base + (size_t)(r + 64) * NPROJ);
        float4 v3 = *(const float4*)(base + (size_t)(r + 65) * NPROJ);
        float4 o;
        o.x = fmaxf(fmaxf(v0.x, v1.x), fmaxf(v2.x, v3.x));
        o.y = fmaxf(fmaxf(v0.y, v1.y), fmaxf(v2.y, v3.y));
        o.z = fmaxf(fmaxf(v0.z, v1.z), fmaxf(v2.z, v3.z));
        o.w = fmaxf(fmaxf(v0.w, v1.w), fmaxf(v2.w, v3.w));
        *((float4*)(phiP + (size_t)bp * 64) + c4) = o;
    } else {
        int j = i - NPHI4;
        if (j < NG4) {
            int bp = j >> 6, c4 = j & 63;
            int b = bp >> 10, ij = bp & 1023, ii = ij >> 5, jj = ij & 31;
            int r = b * 4096 + ii * 128 + jj * 2;
            const float* base = proj + 128 + (size_t)c4 * 4;  // g cols start at 128
            float4 v0 = *(const float4*)(base + (size_t)r * NPROJ);
            float4 v1 = *(const float4*)(base + (size_t)(r + 1) * NPROJ);
            float4 v2 = *(const float4*)(base + (size_t)(r + 64) * NPROJ);
            float4 v3 = *(const float4*)(base + (size_t)(r + 65) * NPROJ);
            float4 o;
            o.x = fmaxf(fmaxf(v0.x, v1.x), fmaxf(v2.x, v3.x));
            o.y = fmaxf(fmaxf(v0.y, v1.y), fmaxf(v2.y, v3.y));
            o.z = fmaxf(fmaxf(v0.z, v1.z), fmaxf(v2.z, v3.z));
            o.w = fmaxf(fmaxf(v0.w, v1.w), fmaxf(v2.w, v3.w));
            *((float4*)(gP + (size_t)bp * 256) + c4) = o;
        }
    }
}

// ---------------- flash attention: tmp = softmax(theta @ phi^T) @ g ----------------
// Block = 64 queries of one batch; 16 key-tiles of 64. 256 threads = 8 warps.
// Scores: warp w owns q rows w*8..w*8+8, lane owns keys lane*2, lane*2+1.
// PV:     warp w owns same 8 q rows; lane owns v-cols lane*8..lane*8+8.
__global__ __launch_bounds__(256, 1) void attn_k(
    const float* __restrict__ proj, const float* __restrict__ phiP,
    const float* __restrict__ gP, float* __restrict__ tmp)
{
    extern __shared__ float sm[];
    float* thT = sm;                 // [d=64][68] transposed theta tile
    float* phT = sm + 64 * 68;       // [d=64][68] transposed phi tile
    float* ps  = sm + 2 * 64 * 68;   // [q=64][68] probabilities
    float* gs  = sm + 3 * 64 * 68;   // [k=64][256] g tile

    const int tid  = threadIdx.x;
    const int lane = tid & 31;
    const int wid  = tid >> 5;
    const int b  = blockIdx.y;
    const int qt = blockIdx.x;
    const int qbase = b * SEQ_Q + qt * 64;

    // load theta tile transposed: thT[d][q] (theta = proj cols 0..64, row stride NPROJ)
    #pragma unroll
    for (int idx = tid; idx < 64 * 16; idx += 256) {
        int q = idx >> 4, d4 = idx & 15;
        float4 v = *(const float4*)(proj + (size_t)(qbase + q) * NPROJ + d4 * 4);
        thT[(d4 * 4 + 0) * 68 + q] = v.x;
        thT[(d4 * 4 + 1) * 68 + q] = v.y;
        thT[(d4 * 4 + 2) * 68 + q] = v.z;
        thT[(d4 * 4 + 3) * 68 + q] = v.w;
    }

    float m[8], l[8], acc[8][8];
    #pragma unroll
    for (int i = 0; i < 8; i++) {
        m[i] = -1e30f; l[i] = 0.f;
        #pragma unroll
        for (int v = 0; v < 8; v++) acc[i][v] = 0.f;
    }

    for (int kt = 0; kt < 16; kt++) {
        __syncthreads();   // prior tile fully consumed (also covers thT stores at kt=0)
        const int kb = b * SEQ_K + kt * 64;
        #pragma unroll
        for (int idx = tid; idx < 64 * 16; idx += 256) {
            int kq = idx >> 4, d4 = idx & 15;
            float4 v = *(const float4*)(phiP + (size_t)(kb + kq) * 64 + d4 * 4);
            phT[(d4 * 4 + 0) * 68 + kq] = v.x;
            phT[(d4 * 4 + 1) * 68 + kq] = v.y;
            phT[(d4 * 4 + 2) * 68 + kq] = v.z;
            phT[(d4 * 4 + 3) * 68 + kq] = v.w;
        }
        #pragma unroll
        for (int idx = tid; idx < 64 * 64; idx += 256) {
            int kr = idx >> 6, c4 = idx & 63;
            *(float4*)&gs[kr * 256 + c4 * 4] =
                *(const float4*)(gP + (size_t)(kb + kr) * 256 + c4 * 4);
        }
        __syncthreads();

        // scores: s[8 q][2 k]
        float s[8][2];
        #pragma unroll
        for (int i = 0; i < 8; i++) { s[i][0] = 0.f; s[i][1] = 0.f; }
        #pragma unroll 8
        for (int d = 0; d < 64; d++) {
            float4 a0 = *(const float4*)&thT[d * 68 + wid * 8];
            float4 a1 = *(const float4*)&thT[d * 68 + wid * 8 + 4];
            float2 bb = *(const float2*)&phT[d * 68 + lane * 2];
            float ar[8] = {a0.x, a0.y, a0.z, a0.w, a1.x, a1.y, a1.z, a1.w};
            #pragma unroll
            for (int i = 0; i < 8; i++) {
                s[i][0] = fmaf(ar[i], bb.x, s[i][0]);
                s[i][1] = fmaf(ar[i], bb.y, s[i][1]);
            }
        }

        // online softmax (full-warp reductions; all lanes end with row stats)
        #pragma unroll
        for (int i = 0; i < 8; i++) {
            float t = fmaxf(s[i][0], s[i][1]);
            #pragma unroll
            for (int o = 16; o >= 1; o >>= 1)
                t = fmaxf(t, __shfl_xor_sync(0xffffffffu, t, o));
            float mn = fmaxf(m[i], t);
            float sc = __expf(m[i] - mn);
            m[i] = mn;
            float p0 = __expf(s[i][0] - mn);
            float p1 = __expf(s[i][1] - mn);
            float r = p0 + p1;
            #pragma unroll
            for (int o = 16; o >= 1; o >>= 1)
                r += __shfl_xor_sync(0xffffffffu, r, o);
            l[i] = l[i] * sc + r;
            #pragma unroll
            for (int v = 0; v < 8; v++) acc[i][v] *= sc;
            ps[(wid * 8 + i) * 68 + lane * 2 + 0] = p0;
            ps[(wid * 8 + i) * 68 + lane * 2 + 1] = p1;
        }
        __syncwarp();   // ps rows for this warp are produced & consumed by this warp only

        // PV: acc[q][v] += P[q][k] * g[k][v]
        #pragma unroll 2
        for (int k = 0; k < 64; k++) {
            float4 g0 = *(const float4*)&gs[k * 256 + lane * 8];
            float4 g1 = *(const float4*)&gs[k * 256 + lane * 8 + 4];
            #pragma unroll
            for (int i = 0; i < 8; i++) {
                float pk = ps[(wid * 8 + i) * 68 + k];
                acc[i][0] = fmaf(pk, g0.x, acc[i][0]);
                acc[i][1] = fmaf(pk, g0.y, acc[i][1]);
                acc[i][2] = fmaf(pk, g0.z, acc[i][2]);
                acc[i][3] = fmaf(pk, g0.w, acc[i][3]);
                acc[i][4] = fmaf(pk, g1.x, acc[i][4]);
                acc[i][5] = fmaf(pk, g1.y, acc[i][5]);
                acc[i][6] = fmaf(pk, g1.z, acc[i][6]);
                acc[i][7] = fmaf(pk, g1.w, acc[i][7]);
            }
        }
    }

    // normalize and write tmp[q][v]
    #pragma unroll
    for (int i = 0; i < 8; i++) {
        float inv = 1.f / l[i];
        size_t row = (size_t)(qbase + wid * 8 + i) * 256 + lane * 8;
        float4 o0 = make_float4(acc[i][0] * inv, acc[i][1] * inv, acc[i][2] * inv, acc[i][3] * inv);
        float4 o1 = make_float4(acc[i][4] * inv, acc[i][5] * inv, acc[i][6] * inv, acc[i][7] * inv);
        *(float4*)(tmp + row)     = o0;
        *(float4*)(tmp + row + 4) = o1;
    }
}

// ---------------- launch ----------------
extern "C" void kernel_launch(void* const* d_in, const int* in_sizes, int n_in,
                              void* d_out, int out_size)
{
    const float* x     = (const float*)d_in[0];
    const float* Wt    = (const float*)d_in[1];
    const float* Wp    = (const float*)d_in[2];
    const float* Wg    = (const float*)d_in[3];
    const float* Wo    = (const float*)d_in[4];
    const float* gamma = (const float*)d_in[5];
    float* out = (float*)d_out;

    float *proj, *phiP, *gP, *tmp, *Wcat;
    cudaGetSymbolAddress((void**)&proj, g_proj);
    cudaGetSymbolAddress((void**)&phiP, g_phiP);
    cudaGetSymbolAddress((void**)&gP,   g_gP);
    cudaGetSymbolAddress((void**)&tmp,  g_tmp);
    cudaGetSymbolAddress((void**)&Wcat, g_Wcat);

    const int ATTN_SMEM = (3 * 64 * 68 + 64 * 256) * 4;  // 117760 B
    cudaFuncSetAttribute(attn_k, cudaFuncAttributeMaxDynamicSharedMemorySize, ATTN_SMEM);

    // 1. pack weights [Wt|Wp|Wg] -> Wcat[512, 384]
    pack_k<<<(C_IN * NPROJ + 255) / 256, 256>>>(Wt, Wp, Wg, Wcat);
    // 2. fused projection: proj = x @ Wcat   (M=65536, N=384, K=512)
    gemm128<<<dim3(NPROJ / 128, M_ROWS / 128), 256>>>(x, Wcat, proj,
        M_ROWS, NPROJ, C_IN, nullptr, nullptr);
    // 3. 2x2 maxpool on phi/g columns
    {
        int total = BATCH * SEQ_K * (D_DIM / 4) + BATCH * SEQ_K * (V_DIM / 4);
        pool_k<<<(total + 255) / 256, 256>>>(proj, phiP, gP);
    }
    // 4. fused softmax attention
    attn_k<<<dim3(SEQ_Q / 64, BATCH), 256, ATTN_SMEM>>>(proj, phiP, gP, tmp);
    // 5. output projection + residual: out = gamma * (tmp @ Wo) + x
    gemm128<<<dim3(C_IN / 128, M_ROWS / 128), 256>>>(tmp, Wo, out,
        M_ROWS, C_IN, V_DIM, x, gamma);
}

// round 5
// speedup vs baseline: 3.3658x; 1.9680x over previous
#include <cuda_runtime.h>
#include <cuda_bf16.h>
#include <math.h>
#include <cstdint>

// x: [16, 64, 64, 512] -> rows M = 65536, C = 512
#define M_ROWS 65536
#define C_IN   512
#define D_DIM  64
#define V_DIM  256
#define BATCH  16
#define SEQ_Q  4096
#define SEQ_K  1024
#define NPROJ  384   // 64 theta | 64 phi | 256 g

// ---------------- scratch (device globals; no allocation allowed) ----------------
__device__ float          g_proj [M_ROWS * NPROJ];          // 96 MB
__device__ float          g_phiP [BATCH * SEQ_K * D_DIM];   //  4 MB
__device__ float          g_gP   [BATCH * SEQ_K * V_DIM];   // 16 MB
__device__ __nv_bfloat16  g_xhi  [M_ROWS * C_IN];           // 64 MB
__device__ __nv_bfloat16  g_xlo  [M_ROWS * C_IN];           // 64 MB
__device__ __nv_bfloat16  g_thi  [M_ROWS * V_DIM];          // 32 MB (tmp hi)
__device__ __nv_bfloat16  g_tlo  [M_ROWS * V_DIM];          // 32 MB (tmp lo)
__device__ __nv_bfloat16  g_Bp_hi[NPROJ * C_IN];            // proj weights [N=384,K=512]
__device__ __nv_bfloat16  g_Bp_lo[NPROJ * C_IN];
__device__ __nv_bfloat16  g_Bo_hi[C_IN * V_DIM];            // Wo weights [N=512,K=256]
__device__ __nv_bfloat16  g_Bo_lo[C_IN * V_DIM];

// ================= baseline-ISA helpers (valid on sm_103 base target) =================
__device__ __forceinline__ uint32_t smem_u32(const void* p) {
    uint32_t a;
    asm("{ .reg .u64 t; cvta.to.shared.u64 t, %1; cvt.u32.u64 %0, t; }" : "=r"(a) : "l"(p));
    return a;
}
#define CP_ASYNC16(dst, src) \
    asm volatile("cp.async.cg.shared.global [%0], [%1], 16;" :: "r"(dst), "l"(src))
#define CP_COMMIT() asm volatile("cp.async.commit_group;" ::: "memory")
#define CP_WAIT(N)  asm volatile("cp.async.wait_group %0;" :: "n"(N) : "memory")
#define LDSM_X4(r0, r1, r2, r3, addr) \
    asm volatile("ldmatrix.sync.aligned.m8n8.x4.shared.b16 {%0,%1,%2,%3}, [%4];" \
                 : "=r"(r0), "=r"(r1), "=r"(r2), "=r"(r3) : "r"(addr))
#define MMA16816(d, a, b0v, b1v) \
    asm volatile("mma.sync.aligned.m16n8k16.row.col.f32.bf16.bf16.f32 " \
                 "{%0,%1,%2,%3}, {%4,%5,%6,%7}, {%8,%9}, {%0,%1,%2,%3};" \
                 : "+f"((d)[0]), "+f"((d)[1]), "+f"((d)[2]), "+f"((d)[3]) \
                 : "r"((a)[0]), "r"((a)[1]), "r"((a)[2]), "r"((a)[3]), \
                   "r"(b0v), "r"(b1v))

// ================= conversion / packing =================
__global__ void convert_x_k(const float* __restrict__ x,
                            __nv_bfloat16* __restrict__ xhi, __nv_bfloat16* __restrict__ xlo)
{
    size_t i = ((size_t)blockIdx.x * blockDim.x + threadIdx.x) * 8;
    if (i >= (size_t)M_ROWS * C_IN) return;
    float4 a = *(const float4*)(x + i);
    float4 b = *(const float4*)(x + i + 4);
    float v[8] = {a.x, a.y, a.z, a.w, b.x, b.y, b.z, b.w};
    __nv_bfloat16 h[8], l[8];
    #pragma unroll
    for (int j = 0; j < 8; j++) {
        h[j] = __float2bfloat16(v[j]);
        l[j] = __float2bfloat16(v[j] - __bfloat162float(h[j]));
    }
    *(uint4*)(xhi + i) = *(const uint4*)h;
    *(uint4*)(xlo + i) = *(const uint4*)l;
}

__global__ void pack_proj_k(const float* __restrict__ Wt, const float* __restrict__ Wp,
                            const float* __restrict__ Wg,
                            __nv_bfloat16* __restrict__ bhi, __nv_bfloat16* __restrict__ blo)
{
    int i = blockIdx.x * blockDim.x + threadIdx.x;
    if (i >= NPROJ * C_IN) return;
    int n = i / C_IN, k = i % C_IN;
    float v;
    if (n < 64)       v = Wt[k * 64 + n];
    else if (n < 128) v = Wp[k * 64 + (n - 64)];
    else              v = Wg[k * 256 + (n - 128)];
    __nv_bfloat16 h = __float2bfloat16(v);
    bhi[i] = h;
    blo[i] = __float2bfloat16(v - __bfloat162float(h));
}

__global__ void pack_wo_k(const float* __restrict__ Wo,
                          __nv_bfloat16* __restrict__ bhi, __nv_bfloat16* __restrict__ blo)
{
    int i = blockIdx.x * blockDim.x + threadIdx.x;
    if (i >= C_IN * V_DIM) return;
    int n = i / V_DIM, k = i % V_DIM;
    float v = Wo[k * C_IN + n];
    __nv_bfloat16 h = __float2bfloat16(v);
    bhi[i] = h;
    blo[i] = __float2bfloat16(v - __bfloat162float(h));
}

// ================= mma.sync split-bf16 GEMM =================
// C[M, ldc](n-block) = A @ B^T, A=[M,KB] hi/lo, B=[Ntot,KB] hi/lo (B^T layout: n rows, k contig)
// 3 terms via region loop: [Ahi*Bhi, Alo*Bhi, Ahi*Blo]. fp32 accumulate in registers.
// 128x128x32 tile, 8 warps (2m x 4n), warp tile 64x32, mma m16n8k16.
// Optional epilogue: C = gamma * acc + res.
#define BK      32
#define ASTRIDE 40   // padded bf16 row stride (80 bytes): conflict-free ldmatrix

template <int KB>
__global__ __launch_bounds__(256, 2) void gemm_mma(
    const __nv_bfloat16* __restrict__ Ahi, const __nv_bfloat16* __restrict__ Alo,
    const __nv_bfloat16* __restrict__ Bhi, const __nv_bfloat16* __restrict__ Blo,
    float* __restrict__ C, int ldc,
    const float* __restrict__ res, const float* __restrict__ gammaP)
{
    __shared__ __align__(16) __nv_bfloat16 sA[2][128 * ASTRIDE];
    __shared__ __align__(16) __nv_bfloat16 sB[2][128 * ASTRIDE];

    const int tid  = threadIdx.x;
    const int lane = tid & 31;
    const int wid  = tid >> 5;
    const int warpM = wid >> 2;     // 0..1 -> 64 rows each
    const int warpN = wid & 3;      // 0..3 -> 32 cols each
    const int m0 = blockIdx.y * 128;
    const int n0 = blockIdx.x * 128;

    constexpr int KPC = KB / BK;       // chunks per region
    constexpr int CHUNKS = 3 * KPC;

    const uint32_t sA0 = smem_u32(sA[0]), sA1 = smem_u32(sA[1]);
    const uint32_t sB0 = smem_u32(sB[0]), sB1 = smem_u32(sB[1]);

    // cp.async one 128x32 bf16 chunk of A and B into buffer `buf`
    auto load_chunk = [&](int c, int buf) {
        const int reg  = c / KPC;
        const int kcol = (c - reg * KPC) * BK;
        const __nv_bfloat16* As = (reg == 1) ? Alo : Ahi;
        const __nv_bfloat16* Bs = (reg == 2) ? Blo : Bhi;
        const uint32_t aB = buf ? sA1 : sA0;
        const uint32_t bB = buf ? sB1 : sB0;
        #pragma unroll
        for (int it = 0; it < 2; it++) {
            int idx = tid + it * 256;
            int row = idx >> 2, c16 = idx & 3;          // 4 x 16B per 64B row
            uint32_t dsta = aB + (row * ASTRIDE + c16 * 8) * 2;
            const __nv_bfloat16* srca = As + (size_t)(m0 + row) * KB + kcol + c16 * 8;
            CP_ASYNC16(dsta, srca);
            uint32_t dstb = bB + (row * ASTRIDE + c16 * 8) * 2;
            const __nv_bfloat16* srcb = Bs + (size_t)(n0 + row) * KB + kcol + c16 * 8;
            CP_ASYNC16(dstb, srcb);
        }
        CP_COMMIT();
    };

    float acc[4][4][4];
    #pragma unroll
    for (int i = 0; i < 4; i++)
        #pragma unroll
        for (int j = 0; j < 4; j++)
            #pragma unroll
            for (int r = 0; r < 4; r++) acc[i][j][r] = 0.f;

    load_chunk(0, 0);

    for (int c = 0; c < CHUNKS; c++) {
        const int buf = c & 1;
        if (c + 1 < CHUNKS) {
            load_chunk(c + 1, buf ^ 1);
            CP_WAIT(1);
        } else {
            CP_WAIT(0);
        }
        __syncthreads();

        const uint32_t aB = buf ? sA1 : sA0;
        const uint32_t bB = buf ? sB1 : sB0;
        #pragma unroll
        for (int k0 = 0; k0 < BK; k0 += 16) {
            uint32_t af[4][4];
            #pragma unroll
            for (int i = 0; i < 4; i++) {
                uint32_t addr = aB +
                    ((warpM * 64 + i * 16 + (lane & 15)) * ASTRIDE + k0 + (lane >> 4) * 8) * 2;
                LDSM_X4(af[i][0], af[i][1], af[i][2], af[i][3], addr);
            }
            uint32_t bf[2][4];
            #pragma unroll
            for (int j2 = 0; j2 < 2; j2++) {
                int g = lane >> 3, r = lane & 7;
                uint32_t addr = bB +
                    ((warpN * 32 + j2 * 16 + (g & 2) * 4 + r) * ASTRIDE + k0 + (g & 1) * 8) * 2;
                LDSM_X4(bf[j2][0], bf[j2][1], bf[j2][2], bf[j2][3], addr);
            }
            #pragma unroll
            for (int i = 0; i < 4; i++)
                #pragma unroll
                for (int j = 0; j < 4; j++)
                    MMA16816(acc[i][j], af[i], bf[j >> 1][(j & 1) * 2], bf[j >> 1][(j & 1) * 2 + 1]);
        }
        __syncthreads();
    }

    // epilogue: acc (i,j) tile rows gr/gr+8, cols gc..gc+1
    const float gamma = res ? *gammaP : 0.f;
    #pragma unroll
    for (int i = 0; i < 4; i++) {
        #pragma unroll
        for (int j = 0; j < 4; j++) {
            int gr = m0 + warpM * 64 + i * 16 + (lane >> 2);
            int gc = n0 + warpN * 32 + j * 8 + (lane & 3) * 2;
            size_t off0 = (size_t)gr * ldc + gc;
            size_t off1 = off0 + (size_t)8 * ldc;
            if (res) {
                float2 r0 = *(const float2*)(res + off0);
                float2 r1 = *(const float2*)(res + off1);
                float2 o0, o1;
                o0.x = fmaf(gamma, acc[i][j][0], r0.x);
                o0.y = fmaf(gamma, acc[i][j][1], r0.y);
                o1.x = fmaf(gamma, acc[i][j][2], r1.x);
                o1.y = fmaf(gamma, acc[i][j][3], r1.y);
                *(float2*)(C + off0) = o0;
                *(float2*)(C + off1) = o1;
            } else {
                *(float2*)(C + off0) = make_float2(acc[i][j][0], acc[i][j][1]);
                *(float2*)(C + off1) = make_float2(acc[i][j][2], acc[i][j][3]);
            }
        }
    }
}

// ---------------- 2x2 maxpool: proj(phi|g cols) -> phiP/gP ----------------
__global__ void pool_k(const float* __restrict__ proj,
                       float* __restrict__ phiP, float* __restrict__ gP)
{
    const int NPHI4 = BATCH * SEQ_K * (D_DIM / 4);
    const int NG4   = BATCH * SEQ_K * (V_DIM / 4);
    int i = blockIdx.x * blockDim.x + threadIdx.x;
    if (i < NPHI4) {
        int bp = i >> 4, c4 = i & 15;
        int b = bp >> 10, ij = bp & 1023, ii = ij >> 5, jj = ij & 31;
        int r = b * 4096 + ii * 128 + jj * 2;
        const float* base = proj + 64 + (size_t)c4 * 4;
        float4 v0 = *(const float4*)(base + (size_t)r * NPROJ);
        float4 v1 = *(const float4*)(base + (size_t)(r + 1) * NPROJ);
        float4 v2 = *(const float4*)(base + (size_t)(r + 64) * NPROJ);
        float4 v3 = *(const float4*)(base + (size_t)(r + 65) * NPROJ);
        float4 o;
        o.x = fmaxf(fmaxf(v0.x, v1.x), fmaxf(v2.x, v3.x));
        o.y = fmaxf(fmaxf(v0.y, v1.y), fmaxf(v2.y, v3.y));
        o.z = fmaxf(fmaxf(v0.z, v1.z), fmaxf(v2.z, v3.z));
        o.w = fmaxf(fmaxf(v0.w, v1.w), fmaxf(v2.w, v3.w));
        *((float4*)(phiP + (size_t)bp * 64) + c4) = o;
    } else {
        int j = i - NPHI4;
        if (j < NG4) {
            int bp = j >> 6, c4 = j & 63;
            int b = bp >> 10, ij = bp & 1023, ii = ij >> 5, jj = ij & 31;
            int r = b * 4096 + ii * 128 + jj * 2;
            const float* base = proj + 128 + (size_t)c4 * 4;
            float4 v0 = *(const float4*)(base + (size_t)r * NPROJ);
            float4 v1 = *(const float4*)(base + (size_t)(r + 1) * NPROJ);
            float4 v2 = *(const float4*)(base + (size_t)(r + 64) * NPROJ);
            float4 v3 = *(const float4*)(base + (size_t)(r + 65) * NPROJ);
            float4 o;
            o.x = fmaxf(fmaxf(v0.x, v1.x), fmaxf(v2.x, v3.x));
            o.y = fmaxf(fmaxf(v0.y, v1.y), fmaxf(v2.y, v3.y));
            o.z = fmaxf(fmaxf(v0.z, v1.z), fmaxf(v2.z, v3.z));
            o.w = fmaxf(fmaxf(v0.w, v1.w), fmaxf(v2.w, v3.w));
            *((float4*)(gP + (size_t)bp * 256) + c4) = o;
        }
    }
}

// ---------------- flash attention (fp32), outputs tmp as bf16 hi/lo ----------------
__global__ __launch_bounds__(256, 1) void attn_k(
    const float* __restrict__ proj, const float* __restrict__ phiP,
    const float* __restrict__ gP,
    __nv_bfloat16* __restrict__ thi, __nv_bfloat16* __restrict__ tlo)
{
    extern __shared__ float sm[];
    float* thT = sm;                 // [64][68]
    float* phT = sm + 64 * 68;       // [64][68]
    float* ps  = sm + 2 * 64 * 68;   // [64][68]
    float* gs  = sm + 3 * 64 * 68;   // [64][256]

    const int tid  = threadIdx.x;
    const int lane = tid & 31;
    const int wid  = tid >> 5;
    const int b  = blockIdx.y;
    const int qt = blockIdx.x;
    const int qbase = b * SEQ_Q + qt * 64;

    #pragma unroll
    for (int idx = tid; idx < 64 * 16; idx += 256) {
        int q = idx >> 4, d4 = idx & 15;
        float4 v = *(const float4*)(proj + (size_t)(qbase + q) * NPROJ + d4 * 4);
        thT[(d4 * 4 + 0) * 68 + q] = v.x;
        thT[(d4 * 4 + 1) * 68 + q] = v.y;
        thT[(d4 * 4 + 2) * 68 + q] = v.z;
        thT[(d4 * 4 + 3) * 68 + q] = v.w;
    }

    float m[8], l[8], acc[8][8];
    #pragma unroll
    for (int i = 0; i < 8; i++) {
        m[i] = -1e30f; l[i] = 0.f;
        #pragma unroll
        for (int v = 0; v < 8; v++) acc[i][v] = 0.f;
    }

    for (int kt = 0; kt < 16; kt++) {
        __syncthreads();
        const int kb = b * SEQ_K + kt * 64;
        #pragma unroll
        for (int idx = tid; idx < 64 * 16; idx += 256) {
            int kq = idx >> 4, d4 = idx & 15;
            float4 v = *(const float4*)(phiP + (size_t)(kb + kq) * 64 + d4 * 4);
            phT[(d4 * 4 + 0) * 68 + kq] = v.x;
            phT[(d4 * 4 + 1) * 68 + kq] = v.y;
            phT[(d4 * 4 + 2) * 68 + kq] = v.z;
            phT[(d4 * 4 + 3) * 68 + kq] = v.w;
        }
        #pragma unroll
        for (int idx = tid; idx < 64 * 64; idx += 256) {
            int kr = idx >> 6, c4 = idx & 63;
            *(float4*)&gs[kr * 256 + c4 * 4] =
                *(const float4*)(gP + (size_t)(kb + kr) * 256 + c4 * 4);
        }
        __syncthreads();

        float s[8][2];
        #pragma unroll
        for (int i = 0; i < 8; i++) { s[i][0] = 0.f; s[i][1] = 0.f; }
        #pragma unroll 8
        for (int d = 0; d < 64; d++) {
            float4 a0 = *(const float4*)&thT[d * 68 + wid * 8];
            float4 a1 = *(const float4*)&thT[d * 68 + wid * 8 + 4];
            float2 bb = *(const float2*)&phT[d * 68 + lane * 2];
            float ar[8] = {a0.x, a0.y, a0.z, a0.w, a1.x, a1.y, a1.z, a1.w};
            #pragma unroll
            for (int i = 0; i < 8; i++) {
                s[i][0] = fmaf(ar[i], bb.x, s[i][0]);
                s[i][1] = fmaf(ar[i], bb.y, s[i][1]);
            }
        }

        #pragma unroll
        for (int i = 0; i < 8; i++) {
            float t = fmaxf(s[i][0], s[i][1]);
            #pragma unroll
            for (int o = 16; o >= 1; o >>= 1)
                t = fmaxf(t, __shfl_xor_sync(0xffffffffu, t, o));
            float mn = fmaxf(m[i], t);
            float sc = __expf(m[i] - mn);
            m[i] = mn;
            float p0 = __expf(s[i][0] - mn);
            float p1 = __expf(s[i][1] - mn);
            float r = p0 + p1;
            #pragma unroll
            for (int o = 16; o >= 1; o >>= 1)
                r += __shfl_xor_sync(0xffffffffu, r, o);
            l[i] = l[i] * sc + r;
            #pragma unroll
            for (int v = 0; v < 8; v++) acc[i][v] *= sc;
            ps[(wid * 8 + i) * 68 + lane * 2 + 0] = p0;
            ps[(wid * 8 + i) * 68 + lane * 2 + 1] = p1;
        }
        __syncwarp();

        #pragma unroll 2
        for (int k = 0; k < 64; k++) {
            float4 g0 = *(const float4*)&gs[k * 256 + lane * 8];
            float4 g1 = *(const float4*)&gs[k * 256 + lane * 8 + 4];
            #pragma unroll
            for (int i = 0; i < 8; i++) {
                float pk = ps[(wid * 8 + i) * 68 + k];
                acc[i][0] = fmaf(pk, g0.x, acc[i][0]);
                acc[i][1] = fmaf(pk, g0.y, acc[i][1]);
                acc[i][2] = fmaf(pk, g0.z, acc[i][2]);
                acc[i][3] = fmaf(pk, g0.w, acc[i][3]);
                acc[i][4] = fmaf(pk, g1.x, acc[i][4]);
                acc[i][5] = fmaf(pk, g1.y, acc[i][5]);
                acc[i][6] = fmaf(pk, g1.z, acc[i][6]);
                acc[i][7] = fmaf(pk, g1.w, acc[i][7]);
            }
        }
    }

    // normalize and write tmp hi/lo (bf16 split) — feeds the mma.sync Wo GEMM
    #pragma unroll
    for (int i = 0; i < 8; i++) {
        float inv = 1.f / l[i];
        size_t row = (size_t)(qbase + wid * 8 + i) * 256 + lane * 8;
        __nv_bfloat16 h8[8], l8[8];
        #pragma unroll
        for (int v = 0; v < 8; v++) {
            float f = acc[i][v] * inv;
            h8[v] = __float2bfloat16(f);
            l8[v] = __float2bfloat16(f - __bfloat162float(h8[v]));
        }
        *(uint4*)(thi + row) = *(const uint4*)h8;
        *(uint4*)(tlo + row) = *(const uint4*)l8;
    }
}

// ---------------- launch ----------------
extern "C" void kernel_launch(void* const* d_in, const int* in_sizes, int n_in,
                              void* d_out, int out_size)
{
    const float* x     = (const float*)d_in[0];
    const float* Wt    = (const float*)d_in[1];
    const float* Wp    = (const float*)d_in[2];
    const float* Wg    = (const float*)d_in[3];
    const float* Wo    = (const float*)d_in[4];
    const float* gamma = (const float*)d_in[5];
    float* out = (float*)d_out;

    float *proj, *phiP, *gP;
    __nv_bfloat16 *xhi, *xlo, *thi, *tlo, *Bph, *Bpl, *Boh, *Bol;
    cudaGetSymbolAddress((void**)&proj, g_proj);
    cudaGetSymbolAddress((void**)&phiP, g_phiP);
    cudaGetSymbolAddress((void**)&gP,   g_gP);
    cudaGetSymbolAddress((void**)&xhi,  g_xhi);
    cudaGetSymbolAddress((void**)&xlo,  g_xlo);
    cudaGetSymbolAddress((void**)&thi,  g_thi);
    cudaGetSymbolAddress((void**)&tlo,  g_tlo);
    cudaGetSymbolAddress((void**)&Bph,  g_Bp_hi);
    cudaGetSymbolAddress((void**)&Bpl,  g_Bp_lo);
    cudaGetSymbolAddress((void**)&Boh,  g_Bo_hi);
    cudaGetSymbolAddress((void**)&Bol,  g_Bo_lo);

    const int ATTN_SMEM = (3 * 64 * 68 + 64 * 256) * 4;  // 117760
    cudaFuncSetAttribute(attn_k, cudaFuncAttributeMaxDynamicSharedMemorySize, ATTN_SMEM);

    // 1. split conversions / weight packs
    convert_x_k<<<(M_ROWS * C_IN / 8 + 255) / 256, 256>>>(x, xhi, xlo);
    pack_proj_k<<<(NPROJ * C_IN + 255) / 256, 256>>>(Wt, Wp, Wg, Bph, Bpl);
    pack_wo_k<<<(C_IN * V_DIM + 255) / 256, 256>>>(Wo, Boh, Bol);
    // 2. fused projection (mma.sync): proj = x @ [Wt|Wp|Wg]
    gemm_mma<512><<<dim3(NPROJ / 128, M_ROWS / 128), 256>>>(
        xhi, xlo, Bph, Bpl, proj, NPROJ, nullptr, nullptr);
    // 3. 2x2 maxpool
    {
        int total = BATCH * SEQ_K * (D_DIM / 4) + BATCH * SEQ_K * (V_DIM / 4);
        pool_k<<<(total + 255) / 256, 256>>>(proj, phiP, gP);
    }
    // 4. fused softmax attention (fp32), emits bf16-split tmp
    attn_k<<<dim3(SEQ_Q / 64, BATCH), 256, ATTN_SMEM>>>(proj, phiP, gP, thi, tlo);
    // 5. output projection (mma.sync) + residual: out = gamma * (tmp @ Wo) + x
    gemm_mma<256><<<dim3(C_IN / 128, M_ROWS / 128), 256>>>(
        thi, tlo, Boh, Bol, out, C_IN, x, gamma);
}

// round 6
// speedup vs baseline: 4.9473x; 1.4699x over previous
#include <cuda_runtime.h>
#include <cuda_bf16.h>
#include <math.h>
#include <cstdint>

// x: [16, 64, 64, 512] -> rows M = 65536, C = 512
#define M_ROWS 65536
#define C_IN   512
#define D_DIM  64
#define V_DIM  256
#define BATCH  16
#define SEQ_Q  4096
#define SEQ_K  1024
#define NPROJ  384   // 64 theta | 64 phi | 256 g

// ---------------- scratch (device globals; no allocation allowed) ----------------
__device__ float          g_proj [M_ROWS * NPROJ];          // 96 MB
__device__ float          g_phiP [BATCH * SEQ_K * D_DIM];   //  4 MB (pooled phi fp32)
__device__ float          g_gP   [BATCH * SEQ_K * V_DIM];   // 16 MB (pooled g fp32)
__device__ __nv_bfloat16  g_xhi  [M_ROWS * C_IN];
__device__ __nv_bfloat16  g_xlo  [M_ROWS * C_IN];
__device__ __nv_bfloat16  g_thi  [M_ROWS * V_DIM];
__device__ __nv_bfloat16  g_tlo  [M_ROWS * V_DIM];
__device__ __nv_bfloat16  g_Bp_hi[NPROJ * C_IN];
__device__ __nv_bfloat16  g_Bp_lo[NPROJ * C_IN];
__device__ __nv_bfloat16  g_Bo_hi[C_IN * V_DIM];
__device__ __nv_bfloat16  g_Bo_lo[C_IN * V_DIM];
__device__ __nv_bfloat16  g_fhi  [BATCH * SEQ_K * D_DIM];   // split phi [b*1024+k][64]
__device__ __nv_bfloat16  g_flo  [BATCH * SEQ_K * D_DIM];
__device__ __nv_bfloat16  g_gth  [BATCH * V_DIM * SEQ_K];   // g transposed [b][v][k]
__device__ __nv_bfloat16  g_gtl  [BATCH * V_DIM * SEQ_K];

// ================= baseline-ISA helpers =================
__device__ __forceinline__ uint32_t smem_u32(const void* p) {
    uint32_t a;
    asm("{ .reg .u64 t; cvta.to.shared.u64 t, %1; cvt.u32.u64 %0, t; }" : "=r"(a) : "l"(p));
    return a;
}
__device__ __forceinline__ float ex2f(float x) {
    float y; asm("ex2.approx.f32 %0, %1;" : "=f"(y) : "f"(x)); return y;
}
#define CP_ASYNC16(dst, src) \
    asm volatile("cp.async.cg.shared.global [%0], [%1], 16;" :: "r"(dst), "l"(src))
#define CP_COMMIT() asm volatile("cp.async.commit_group;" ::: "memory")
#define CP_WAIT(N)  asm volatile("cp.async.wait_group %0;" :: "n"(N) : "memory")
#define LDSM_X4(r0, r1, r2, r3, addr) \
    asm volatile("ldmatrix.sync.aligned.m8n8.x4.shared.b16 {%0,%1,%2,%3}, [%4];" \
                 : "=r"(r0), "=r"(r1), "=r"(r2), "=r"(r3) : "r"(addr))
#define MMA16816(d, a, b0v, b1v) \
    asm volatile("mma.sync.aligned.m16n8k16.row.col.f32.bf16.bf16.f32 " \
                 "{%0,%1,%2,%3}, {%4,%5,%6,%7}, {%8,%9}, {%0,%1,%2,%3};" \
                 : "+f"((d)[0]), "+f"((d)[1]), "+f"((d)[2]), "+f"((d)[3]) \
                 : "r"((a)[0]), "r"((a)[1]), "r"((a)[2]), "r"((a)[3]), \
                   "r"(b0v), "r"(b1v))

// ================= conversion / packing =================
__global__ void convert_x_k(const float* __restrict__ x,
                            __nv_bfloat16* __restrict__ xhi, __nv_bfloat16* __restrict__ xlo)
{
    size_t i = ((size_t)blockIdx.x * blockDim.x + threadIdx.x) * 8;
    if (i >= (size_t)M_ROWS * C_IN) return;
    float4 a = *(const float4*)(x + i);
    float4 b = *(const float4*)(x + i + 4);
    float v[8] = {a.x, a.y, a.z, a.w, b.x, b.y, b.z, b.w};
    __nv_bfloat16 h[8], l[8];
    #pragma unroll
    for (int j = 0; j < 8; j++) {
        h[j] = __float2bfloat16(v[j]);
        l[j] = __float2bfloat16(v[j] - __bfloat162float(h[j]));
    }
    *(uint4*)(xhi + i) = *(const uint4*)h;
    *(uint4*)(xlo + i) = *(const uint4*)l;
}

__global__ void pack_proj_k(const float* __restrict__ Wt, const float* __restrict__ Wp,
                            const float* __restrict__ Wg,
                            __nv_bfloat16* __restrict__ bhi, __nv_bfloat16* __restrict__ blo)
{
    int i = blockIdx.x * blockDim.x + threadIdx.x;
    if (i >= NPROJ * C_IN) return;
    int n = i / C_IN, k = i % C_IN;
    float v;
    if (n < 64)       v = Wt[k * 64 + n];
    else if (n < 128) v = Wp[k * 64 + (n - 64)];
    else              v = Wg[k * 256 + (n - 128)];
    __nv_bfloat16 h = __float2bfloat16(v);
    bhi[i] = h;
    blo[i] = __float2bfloat16(v - __bfloat162float(h));
}

__global__ void pack_wo_k(const float* __restrict__ Wo,
                          __nv_bfloat16* __restrict__ bhi, __nv_bfloat16* __restrict__ blo)
{
    int i = blockIdx.x * blockDim.x + threadIdx.x;
    if (i >= C_IN * V_DIM) return;
    int n = i / V_DIM, k = i % V_DIM;
    float v = Wo[k * C_IN + n];
    __nv_bfloat16 h = __float2bfloat16(v);
    bhi[i] = h;
    blo[i] = __float2bfloat16(v - __bfloat162float(h));
}

// ================= mma.sync split-bf16 GEMM (unchanged from R5) =================
#define BK      32
#define ASTRIDE 40

template <int KB>
__global__ __launch_bounds__(256, 2) void gemm_mma(
    const __nv_bfloat16* __restrict__ Ahi, const __nv_bfloat16* __restrict__ Alo,
    const __nv_bfloat16* __restrict__ Bhi, const __nv_bfloat16* __restrict__ Blo,
    float* __restrict__ C, int ldc,
    const float* __restrict__ res, const float* __restrict__ gammaP)
{
    __shared__ __align__(16) __nv_bfloat16 sA[2][128 * ASTRIDE];
    __shared__ __align__(16) __nv_bfloat16 sB[2][128 * ASTRIDE];

    const int tid  = threadIdx.x;
    const int lane = tid & 31;
    const int wid  = tid >> 5;
    const int warpM = wid >> 2;
    const int warpN = wid & 3;
    const int m0 = blockIdx.y * 128;
    const int n0 = blockIdx.x * 128;

    constexpr int KPC = KB / BK;
    constexpr int CHUNKS = 3 * KPC;

    const uint32_t sA0 = smem_u32(sA[0]), sA1 = smem_u32(sA[1]);
    const uint32_t sB0 = smem_u32(sB[0]), sB1 = smem_u32(sB[1]);

    auto load_chunk = [&](int c, int buf) {
        const int reg  = c / KPC;
        const int kcol = (c - reg * KPC) * BK;
        const __nv_bfloat16* As = (reg == 1) ? Alo : Ahi;
        const __nv_bfloat16* Bs = (reg == 2) ? Blo : Bhi;
        const uint32_t aB = buf ? sA1 : sA0;
        const uint32_t bB = buf ? sB1 : sB0;
        #pragma unroll
        for (int it = 0; it < 2; it++) {
            int idx = tid + it * 256;
            int row = idx >> 2, c16 = idx & 3;
            CP_ASYNC16(aB + (row * ASTRIDE + c16 * 8) * 2,
                       As + (size_t)(m0 + row) * KB + kcol + c16 * 8);
            CP_ASYNC16(bB + (row * ASTRIDE + c16 * 8) * 2,
                       Bs + (size_t)(n0 + row) * KB + kcol + c16 * 8);
        }
        CP_COMMIT();
    };

    float acc[4][4][4];
    #pragma unroll
    for (int i = 0; i < 4; i++)
        #pragma unroll
        for (int j = 0; j < 4; j++)
            #pragma unroll
            for (int r = 0; r < 4; r++) acc[i][j][r] = 0.f;

    load_chunk(0, 0);

    for (int c = 0; c < CHUNKS; c++) {
        const int buf = c & 1;
        if (c + 1 < CHUNKS) { load_chunk(c + 1, buf ^ 1); CP_WAIT(1); }
        else                { CP_WAIT(0); }
        __syncthreads();

        const uint32_t aB = buf ? sA1 : sA0;
        const uint32_t bB = buf ? sB1 : sB0;
        #pragma unroll
        for (int k0 = 0; k0 < BK; k0 += 16) {
            uint32_t af[4][4];
            #pragma unroll
            for (int i = 0; i < 4; i++) {
                uint32_t addr = aB +
                    ((warpM * 64 + i * 16 + (lane & 15)) * ASTRIDE + k0 + (lane >> 4) * 8) * 2;
                LDSM_X4(af[i][0], af[i][1], af[i][2], af[i][3], addr);
            }
            uint32_t bf[2][4];
            #pragma unroll
            for (int j2 = 0; j2 < 2; j2++) {
                int g = lane >> 3, r = lane & 7;
                uint32_t addr = bB +
                    ((warpN * 32 + j2 * 16 + (g & 2) * 4 + r) * ASTRIDE + k0 + (g & 1) * 8) * 2;
                LDSM_X4(bf[j2][0], bf[j2][1], bf[j2][2], bf[j2][3], addr);
            }
            #pragma unroll
            for (int i = 0; i < 4; i++)
                #pragma unroll
                for (int j = 0; j < 4; j++)
                    MMA16816(acc[i][j], af[i], bf[j >> 1][(j & 1) * 2], bf[j >> 1][(j & 1) * 2 + 1]);
        }
        __syncthreads();
    }

    const float gamma = res ? *gammaP : 0.f;
    #pragma unroll
    for (int i = 0; i < 4; i++) {
        #pragma unroll
        for (int j = 0; j < 4; j++) {
            int gr = m0 + warpM * 64 + i * 16 + (lane >> 2);
            int gc = n0 + warpN * 32 + j * 8 + (lane & 3) * 2;
            size_t off0 = (size_t)gr * ldc + gc;
            size_t off1 = off0 + (size_t)8 * ldc;
            if (res) {
                float2 r0 = *(const float2*)(res + off0);
                float2 r1 = *(const float2*)(res + off1);
                float2 o0, o1;
                o0.x = fmaf(gamma, acc[i][j][0], r0.x);
                o0.y = fmaf(gamma, acc[i][j][1], r0.y);
                o1.x = fmaf(gamma, acc[i][j][2], r1.x);
                o1.y = fmaf(gamma, acc[i][j][3], r1.y);
                *(float2*)(C + off0) = o0;
                *(float2*)(C + off1) = o1;
            } else {
                *(float2*)(C + off0) = make_float2(acc[i][j][0], acc[i][j][1]);
                *(float2*)(C + off1) = make_float2(acc[i][j][2], acc[i][j][3]);
            }
        }
    }
}

// ---------------- 2x2 maxpool: proj(phi|g cols) -> phiP/gP fp32 ----------------
__global__ void pool_k(const float* __restrict__ proj,
                       float* __restrict__ phiP, float* __restrict__ gP)
{
    const int NPHI4 = BATCH * SEQ_K * (D_DIM / 4);
    const int NG4   = BATCH * SEQ_K * (V_DIM / 4);
    int i = blockIdx.x * blockDim.x + threadIdx.x;
    if (i < NPHI4) {
        int bp = i >> 4, c4 = i & 15;
        int b = bp >> 10, ij = bp & 1023, ii = ij >> 5, jj = ij & 31;
        int r = b * 4096 + ii * 128 + jj * 2;
        const float* base = proj + 64 + (size_t)c4 * 4;
        float4 v0 = *(const float4*)(base + (size_t)r * NPROJ);
        float4 v1 = *(const float4*)(base + (size_t)(r + 1) * NPROJ);
        float4 v2 = *(const float4*)(base + (size_t)(r + 64) * NPROJ);
        float4 v3 = *(const float4*)(base + (size_t)(r + 65) * NPROJ);
        float4 o;
        o.x = fmaxf(fmaxf(v0.x, v1.x), fmaxf(v2.x, v3.x));
        o.y = fmaxf(fmaxf(v0.y, v1.y), fmaxf(v2.y, v3.y));
        o.z = fmaxf(fmaxf(v0.z, v1.z), fmaxf(v2.z, v3.z));
        o.w = fmaxf(fmaxf(v0.w, v1.w), fmaxf(v2.w, v3.w));
        *((float4*)(phiP + (size_t)bp * 64) + c4) = o;
    } else {
        int j = i - NPHI4;
        if (j < NG4) {
            int bp = j >> 6, c4 = j & 63;
            int b = bp >> 10, ij = bp & 1023, ii = ij >> 5, jj = ij & 31;
            int r = b * 4096 + ii * 128 + jj * 2;
            const float* base = proj + 128 + (size_t)c4 * 4;
            float4 v0 = *(const float4*)(base + (size_t)r * NPROJ);
            float4 v1 = *(const float4*)(base + (size_t)(r + 1) * NPROJ);
            float4 v2 = *(const float4*)(base + (size_t)(r + 64) * NPROJ);
            float4 v3 = *(const float4*)(base + (size_t)(r + 65) * NPROJ);
            float4 o;
            o.x = fmaxf(fmaxf(v0.x, v1.x), fmaxf(v2.x, v3.x));
            o.y = fmaxf(fmaxf(v0.y, v1.y), fmaxf(v2.y, v3.y));
            o.z = fmaxf(fmaxf(v0.z, v1.z), fmaxf(v2.z, v3.z));
            o.w = fmaxf(fmaxf(v0.w, v1.w), fmaxf(v2.w, v3.w));
            *((float4*)(gP + (size_t)bp * 256) + c4) = o;
        }
    }
}

// ---------------- split phi fp32 -> bf16 hi/lo (same layout) ----------------
__global__ void split_phi_k(const float* __restrict__ phiP,
                            __nv_bfloat16* __restrict__ fhi, __nv_bfloat16* __restrict__ flo)
{
    size_t i = ((size_t)blockIdx.x * blockDim.x + threadIdx.x) * 4;
    if (i >= (size_t)BATCH * SEQ_K * D_DIM) return;
    float4 v = *(const float4*)(phiP + i);
    float f[4] = {v.x, v.y, v.z, v.w};
    __nv_bfloat16 h[4], l[4];
    #pragma unroll
    for (int j = 0; j < 4; j++) {
        h[j] = __float2bfloat16(f[j]);
        l[j] = __float2bfloat16(f[j] - __bfloat162float(h[j]));
    }
    *(uint2*)(fhi + i) = *(const uint2*)h;
    *(uint2*)(flo + i) = *(const uint2*)l;
}

// ---------------- transpose+split g: gP[b*1024+k][256] -> gT[b][v][k] hi/lo ----------------
__global__ void transT_g_k(const float* __restrict__ gP,
                           __nv_bfloat16* __restrict__ gth, __nv_bfloat16* __restrict__ gtl)
{
    __shared__ float sm[32][33];
    const int t = threadIdx.x;
    const int v0 = blockIdx.x * 32;
    const int k0 = blockIdx.y * 32;
    const int b  = blockIdx.z;
    {
        int r = t >> 3, cg = t & 7;
        float4 v = *(const float4*)(gP + (size_t)(b * SEQ_K + k0 + r) * V_DIM + v0 + cg * 4);
        sm[r][cg * 4 + 0] = v.x; sm[r][cg * 4 + 1] = v.y;
        sm[r][cg * 4 + 2] = v.z; sm[r][cg * 4 + 3] = v.w;
    }
    __syncthreads();
    {
        int v = t >> 3, kg = t & 7;
        __nv_bfloat16 h[4], l[4];
        #pragma unroll
        for (int j = 0; j < 4; j++) {
            float f = sm[kg * 4 + j][v];
            h[j] = __float2bfloat16(f);
            l[j] = __float2bfloat16(f - __bfloat162float(h[j]));
        }
        size_t off = (size_t)(b * V_DIM + v0 + v) * SEQ_K + k0 + kg * 4;
        *(uint2*)(gth + off) = *(const uint2*)h;
        *(uint2*)(gtl + off) = *(const uint2*)l;
    }
}

// ================= flash attention on mma.sync (split-bf16) =================
// CTA: 128 queries of one batch, 512 threads = 16 warps (4m x 4n). 16 key-tiles of 64.
// QK warp tile 32q x 16k (mf=2, nf=2); PV warp tile 32q x 64v (mf=2, nf=8).
// smem offsets in bf16 elements (stride 72 = 64 + 8 pad, conflict-free ldmatrix):
#define OFF_TH  0u      // theta hi  [128][72]
#define OFF_TL  9216u   // theta lo
#define OFF_FH  18432u  // phi hi    [64][72]
#define OFF_FL  23040u  // phi lo
#define OFF_GH  27648u  // gT hi     [256][72]
#define OFF_GL  46080u
#define OFF_SPH 64512u  // P hi      [128][72]
#define OFF_SPL 73728u
#define ATTN_BF16_ELEMS 82944u
#define ATTN_SMEM_BYTES (82944 * 2 + 2 * 512 * 4)  // 169984

__global__ __launch_bounds__(512, 1) void attn_k(
    const float* __restrict__ proj,
    const __nv_bfloat16* __restrict__ fhi, const __nv_bfloat16* __restrict__ flo,
    const __nv_bfloat16* __restrict__ gth, const __nv_bfloat16* __restrict__ gtl,
    __nv_bfloat16* __restrict__ thi, __nv_bfloat16* __restrict__ tlo)
{
    extern __shared__ __nv_bfloat16 sb[];
    float* redA = (float*)(sb + ATTN_BF16_ELEMS);
    float* redB = redA + 512;

    const uint32_t sb32 = smem_u32(sb);
    const int tid  = threadIdx.x;
    const int lane = tid & 31;
    const int wid  = tid >> 5;
    const int warpM = wid >> 2;     // 0..3: 32 q-rows each
    const int warpN = wid & 3;      // QK: 16 keys each; PV: 64 v-cols each
    const int b  = blockIdx.y;
    const int qt = blockIdx.x;
    const int qbase = b * SEQ_Q + qt * 128;
    const float L2E = 1.4426950408889634f;

    // ---- prologue: theta (scaled by log2e) -> smem hi/lo ----
    #pragma unroll
    for (int i = tid; i < 128 * 16; i += 512) {
        int q = i >> 4, c4 = i & 15;
        float4 v = *(const float4*)(proj + (size_t)(qbase + q) * NPROJ + c4 * 4);
        float f[4] = {v.x * L2E, v.y * L2E, v.z * L2E, v.w * L2E};
        __nv_bfloat16 h[4], l[4];
        #pragma unroll
        for (int j = 0; j < 4; j++) {
            h[j] = __float2bfloat16(f[j]);
            l[j] = __float2bfloat16(f[j] - __bfloat162float(h[j]));
        }
        uint32_t o = q * 72 + c4 * 4;
        *(uint2*)(sb + OFF_TH + o) = *(const uint2*)h;
        *(uint2*)(sb + OFF_TL + o) = *(const uint2*)l;
    }
    __syncthreads();

    float acc[2][8][4];
    float m[2][2], l[2][2];
    #pragma unroll
    for (int mf = 0; mf < 2; mf++) {
        m[mf][0] = -1e30f; m[mf][1] = -1e30f;
        l[mf][0] = 0.f;    l[mf][1] = 0.f;
        #pragma unroll
        for (int nf = 0; nf < 8; nf++)
            #pragma unroll
            for (int c = 0; c < 4; c++) acc[mf][nf][c] = 0.f;
    }

    const int rowA = warpM * 32 + (lane & 15);      // ldmatrix A row base (+mf*16)
    const int rq   = lane >> 2;                      // accum row within 8-block
    const int cq2  = (lane & 3) * 2;                 // accum col pair base

    for (int kt = 0; kt < 16; kt++) {
        __syncthreads();   // previous PV reads of gT/P done; red buffers free
        // ---- issue phi tile (group 1), then gT tile (group 0) ----
        {
            const size_t fb = (size_t)(b * SEQ_K + kt * 64) * 64;
            #pragma unroll
            for (int i = 0; i < 2; i++) {
                int id = tid + i * 512;            // 0..1023
                int half = id >> 9, j = id & 511;
                int row = j >> 3, c = j & 7;
                CP_ASYNC16(sb32 + ((half ? OFF_FL : OFF_FH) + row * 72 + c * 8) * 2,
                           (half ? flo : fhi) + fb + (size_t)row * 64 + c * 8);
            }
            CP_COMMIT();
            const size_t gb = (size_t)b * V_DIM * SEQ_K + kt * 64;
            #pragma unroll
            for (int i = 0; i < 8; i++) {
                int id = tid + i * 512;            // 0..4095
                int half = id >> 11, j = id & 2047;
                int v = j >> 3, c = j & 7;
                CP_ASYNC16(sb32 + ((half ? OFF_GL : OFF_GH) + v * 72 + c * 8) * 2,
                           (half ? gtl : gth) + gb + (size_t)v * SEQ_K + c * 8);
            }
            CP_COMMIT();
        }
        CP_WAIT(1);          // phi arrived (gT still in flight)
        __syncthreads();

        // ---- QK: scores[128][64] in log2 domain (theta pre-scaled) ----
        float aq[2][2][4];
        #pragma unroll
        for (int mf = 0; mf < 2; mf++)
            #pragma unroll
            for (int nf = 0; nf < 2; nf++)
                #pragma unroll
                for (int c = 0; c < 4; c++) aq[mf][nf][c] = 0.f;

        #pragma unroll
        for (int reg = 0; reg < 3; reg++) {
            const uint32_t aoff = (reg == 1) ? OFF_TL : OFF_TH;
            const uint32_t boff = (reg == 2) ? OFF_FL : OFF_FH;
            #pragma unroll
            for (int k0 = 0; k0 < 64; k0 += 16) {
                uint32_t a0[4], a1[4], bb[4];
                uint32_t colA = k0 + (lane >> 4) * 8;
                LDSM_X4(a0[0], a0[1], a0[2], a0[3],
                        sb32 + (aoff + (rowA) * 72 + colA) * 2);
                LDSM_X4(a1[0], a1[1], a1[2], a1[3],
                        sb32 + (aoff + (rowA + 16) * 72 + colA) * 2);
                int g = lane >> 3, rr = lane & 7;
                LDSM_X4(bb[0], bb[1], bb[2], bb[3],
                        sb32 + (boff + (warpN * 16 + (g & 2) * 4 + rr) * 72 + k0 + (g & 1) * 8) * 2);
                MMA16816(aq[0][0], a0, bb[0], bb[1]);
                MMA16816(aq[0][1], a0, bb[2], bb[3]);
                MMA16816(aq[1][0], a1, bb[0], bb[1]);
                MMA16816(aq[1][1], a1, bb[2], bb[3]);
            }
        }

        // ---- row max (quad shfl + cross-warpN via smem) ----
        float mx[2][2];
        #pragma unroll
        for (int mf = 0; mf < 2; mf++)
            #pragma unroll
            for (int h = 0; h < 2; h++) {
                float t = fmaxf(fmaxf(aq[mf][0][h * 2], aq[mf][0][h * 2 + 1]),
                                fmaxf(aq[mf][1][h * 2], aq[mf][1][h * 2 + 1]));
                t = fmaxf(t, __shfl_xor_sync(0xffffffffu, t, 1));
                t = fmaxf(t, __shfl_xor_sync(0xffffffffu, t, 2));
                mx[mf][h] = t;
            }
        if ((lane & 3) == 0) {
            #pragma unroll
            for (int mf = 0; mf < 2; mf++)
                #pragma unroll
                for (int h = 0; h < 2; h++)
                    redA[warpN * 128 + warpM * 32 + mf * 16 + h * 8 + rq] = mx[mf][h];
        }
        __syncthreads();

        float mnew[2][2], scale[2][2], rsum[2][2];
        #pragma unroll
        for (int mf = 0; mf < 2; mf++)
            #pragma unroll
            for (int h = 0; h < 2; h++) {
                int r = warpM * 32 + mf * 16 + h * 8 + rq;
                float v = m[mf][h];
                #pragma unroll
                for (int w = 0; w < 4; w++) v = fmaxf(v, redA[w * 128 + r]);
                mnew[mf][h] = v;
                rsum[mf][h] = 0.f;
            }

        // ---- p = exp2(s - mnew); store P hi/lo; partial row sums ----
        #pragma unroll
        for (int mf = 0; mf < 2; mf++)
            #pragma unroll
            for (int nf = 0; nf < 2; nf++)
                #pragma unroll
                for (int h = 0; h < 2; h++) {
                    float p0 = ex2f(aq[mf][nf][h * 2]     - mnew[mf][h]);
                    float p1 = ex2f(aq[mf][nf][h * 2 + 1] - mnew[mf][h]);
                    rsum[mf][h] += p0 + p1;
                    __nv_bfloat16 h0 = __float2bfloat16(p0);
                    __nv_bfloat16 h1 = __float2bfloat16(p1);
                    __nv_bfloat16 l0 = __float2bfloat16(p0 - __bfloat162float(h0));
                    __nv_bfloat16 l1 = __float2bfloat16(p1 - __bfloat162float(h1));
                    int row = warpM * 32 + mf * 16 + h * 8 + rq;
                    int col = warpN * 16 + nf * 8 + cq2;
                    __nv_bfloat162 hv; hv.x = h0; hv.y = h1;
                    __nv_bfloat162 lv; lv.x = l0; lv.y = l1;
                    *(__nv_bfloat162*)(sb + OFF_SPH + row * 72 + col) = hv;
                    *(__nv_bfloat162*)(sb + OFF_SPL + row * 72 + col) = lv;
                }
        #pragma unroll
        for (int mf = 0; mf < 2; mf++)
            #pragma unroll
            for (int h = 0; h < 2; h++) {
                float t = rsum[mf][h];
                t += __shfl_xor_sync(0xffffffffu, t, 1);
                t += __shfl_xor_sync(0xffffffffu, t, 2);
                rsum[mf][h] = t;
                scale[mf][h] = ex2f(m[mf][h] - mnew[mf][h]);
                m[mf][h] = mnew[mf][h];
            }
        if ((lane & 3) == 0) {
            #pragma unroll
            for (int mf = 0; mf < 2; mf++)
                #pragma unroll
                for (int h = 0; h < 2; h++)
                    redB[warpN * 128 + warpM * 32 + mf * 16 + h * 8 + rq] = rsum[mf][h];
        }
        CP_WAIT(0);          // gT arrived (this thread's chunks)
        __syncthreads();     // all threads' chunks + P + redB visible

        #pragma unroll
        for (int mf = 0; mf < 2; mf++)
            #pragma unroll
            for (int h = 0; h < 2; h++) {
                int r = warpM * 32 + mf * 16 + h * 8 + rq;
                float s = 0.f;
                #pragma unroll
                for (int w = 0; w < 4; w++) s += redB[w * 128 + r];
                l[mf][h] = l[mf][h] * scale[mf][h] + s;
            }
        #pragma unroll
        for (int mf = 0; mf < 2; mf++)
            #pragma unroll
            for (int nf = 0; nf < 8; nf++) {
                acc[mf][nf][0] *= scale[mf][0];
                acc[mf][nf][1] *= scale[mf][0];
                acc[mf][nf][2] *= scale[mf][1];
                acc[mf][nf][3] *= scale[mf][1];
            }

        // ---- PV: acc += P @ gT^T ----
        #pragma unroll
        for (int reg = 0; reg < 3; reg++) {
            const uint32_t aoff = (reg == 1) ? OFF_SPL : OFF_SPH;
            const uint32_t boff = (reg == 2) ? OFF_GL : OFF_GH;
            #pragma unroll
            for (int k0 = 0; k0 < 64; k0 += 16) {
                uint32_t a0[4], a1[4];
                uint32_t colA = k0 + (lane >> 4) * 8;
                LDSM_X4(a0[0], a0[1], a0[2], a0[3],
                        sb32 + (aoff + (rowA) * 72 + colA) * 2);
                LDSM_X4(a1[0], a1[1], a1[2], a1[3],
                        sb32 + (aoff + (rowA + 16) * 72 + colA) * 2);
                int g = lane >> 3, rr = lane & 7;
                #pragma unroll
                for (int j2 = 0; j2 < 4; j2++) {
                    uint32_t bb[4];
                    LDSM_X4(bb[0], bb[1], bb[2], bb[3],
                            sb32 + (boff + (warpN * 64 + j2 * 16 + (g & 2) * 4 + rr) * 72
                                    + k0 + (g & 1) * 8) * 2);
                    MMA16816(acc[0][j2 * 2 + 0], a0, bb[0], bb[1]);
                    MMA16816(acc[0][j2 * 2 + 1], a0, bb[2], bb[3]);
                    MMA16816(acc[1][j2 * 2 + 0], a1, bb[0], bb[1]);
                    MMA16816(acc[1][j2 * 2 + 1], a1, bb[2], bb[3]);
                }
            }
        }
    }

    // ---- epilogue: tmp = acc / l -> bf16 hi/lo ----
    #pragma unroll
    for (int mf = 0; mf < 2; mf++)
        #pragma unroll
        for (int h = 0; h < 2; h++) {
            float inv = 1.f / l[mf][h];
            int row = qbase + warpM * 32 + mf * 16 + h * 8 + rq;
            #pragma unroll
            for (int nf = 0; nf < 8; nf++) {
                int col = warpN * 64 + nf * 8 + cq2;
                float v0 = acc[mf][nf][h * 2]     * inv;
                float v1 = acc[mf][nf][h * 2 + 1] * inv;
                __nv_bfloat16 h0 = __float2bfloat16(v0);
                __nv_bfloat16 h1 = __float2bfloat16(v1);
                __nv_bfloat16 l0 = __float2bfloat16(v0 - __bfloat162float(h0));
                __nv_bfloat16 l1 = __float2bfloat16(v1 - __bfloat162float(h1));
                __nv_bfloat162 hv; hv.x = h0; hv.y = h1;
                __nv_bfloat162 lv; lv.x = l0; lv.y = l1;
                *(__nv_bfloat162*)(thi + (size_t)row * V_DIM + col) = hv;
                *(__nv_bfloat162*)(tlo + (size_t)row * V_DIM + col) = lv;
            }
        }
}

// ---------------- launch ----------------
extern "C" void kernel_launch(void* const* d_in, const int* in_sizes, int n_in,
                              void* d_out, int out_size)
{
    const float* x     = (const float*)d_in[0];
    const float* Wt    = (const float*)d_in[1];
    const float* Wp    = (const float*)d_in[2];
    const float* Wg    = (const float*)d_in[3];
    const float* Wo    = (const float*)d_in[4];
    const float* gamma = (const float*)d_in[5];
    float* out = (float*)d_out;

    float *proj, *phiP, *gP;
    __nv_bfloat16 *xhi, *xlo, *thi, *tlo, *Bph, *Bpl, *Boh, *Bol, *fhi, *flo, *gth, *gtl;
    cudaGetSymbolAddress((void**)&proj, g_proj);
    cudaGetSymbolAddress((void**)&phiP, g_phiP);
    cudaGetSymbolAddress((void**)&gP,   g_gP);
    cudaGetSymbolAddress((void**)&xhi,  g_xhi);
    cudaGetSymbolAddress((void**)&xlo,  g_xlo);
    cudaGetSymbolAddress((void**)&thi,  g_thi);
    cudaGetSymbolAddress((void**)&tlo,  g_tlo);
    cudaGetSymbolAddress((void**)&Bph,  g_Bp_hi);
    cudaGetSymbolAddress((void**)&Bpl,  g_Bp_lo);
    cudaGetSymbolAddress((void**)&Boh,  g_Bo_hi);
    cudaGetSymbolAddress((void**)&Bol,  g_Bo_lo);
    cudaGetSymbolAddress((void**)&fhi,  g_fhi);
    cudaGetSymbolAddress((void**)&flo,  g_flo);
    cudaGetSymbolAddress((void**)&gth,  g_gth);
    cudaGetSymbolAddress((void**)&gtl,  g_gtl);

    cudaFuncSetAttribute(attn_k, cudaFuncAttributeMaxDynamicSharedMemorySize, ATTN_SMEM_BYTES);

    // 1. split conversions / weight packs
    convert_x_k<<<(M_ROWS * C_IN / 8 + 255) / 256, 256>>>(x, xhi, xlo);
    pack_proj_k<<<(NPROJ * C_IN + 255) / 256, 256>>>(Wt, Wp, Wg, Bph, Bpl);
    pack_wo_k<<<(C_IN * V_DIM + 255) / 256, 256>>>(Wo, Boh, Bol);
    // 2. fused projection (mma.sync): proj = x @ [Wt|Wp|Wg]
    gemm_mma<512><<<dim3(NPROJ / 128, M_ROWS / 128), 256>>>(
        xhi, xlo, Bph, Bpl, proj, NPROJ, nullptr, nullptr);
    // 3. 2x2 maxpool (fp32) then split/transpose for tensor cores
    {
        int total = BATCH * SEQ_K * (D_DIM / 4) + BATCH * SEQ_K * (V_DIM / 4);
        pool_k<<<(total + 255) / 256, 256>>>(proj, phiP, gP);
    }
    split_phi_k<<<(BATCH * SEQ_K * D_DIM / 4 + 255) / 256, 256>>>(phiP, fhi, flo);
    transT_g_k<<<dim3(V_DIM / 32, SEQ_K / 32, BATCH), 256>>>(gP, gth, gtl);
    // 4. flash attention on mma.sync, emits bf16-split tmp
    attn_k<<<dim3(SEQ_Q / 128, BATCH), 512, ATTN_SMEM_BYTES>>>(
        proj, fhi, flo, gth, gtl, thi, tlo);
    // 5. output projection (mma.sync) + residual: out = gamma * (tmp @ Wo) + x
    gemm_mma<256><<<dim3(C_IN / 128, M_ROWS / 128), 256>>>(
        thi, tlo, Boh, Bol, out, C_IN, x, gamma);
}

// round 7
// speedup vs baseline: 5.0130x; 1.0133x over previous
#include <cuda_runtime.h>
#include <cuda_bf16.h>
#include <math.h>
#include <cstdint>

// x: [16, 64, 64, 512] -> rows M = 65536, C = 512
#define M_ROWS 65536
#define C_IN   512
#define D_DIM  64
#define V_DIM  256
#define BATCH  16
#define SEQ_Q  4096
#define SEQ_K  1024
#define NPROJ  384   // 64 theta | 64 phi | 256 g

// ---------------- scratch (device globals; no allocation allowed) ----------------
__device__ float          g_proj [M_ROWS * NPROJ];
__device__ float          g_phiP [BATCH * SEQ_K * D_DIM];
__device__ float          g_gP   [BATCH * SEQ_K * V_DIM];
__device__ __nv_bfloat16  g_xhi  [M_ROWS * C_IN];
__device__ __nv_bfloat16  g_xlo  [M_ROWS * C_IN];
__device__ __nv_bfloat16  g_thi  [M_ROWS * V_DIM];
__device__ __nv_bfloat16  g_tlo  [M_ROWS * V_DIM];
__device__ __nv_bfloat16  g_Bp_hi[NPROJ * C_IN];
__device__ __nv_bfloat16  g_Bp_lo[NPROJ * C_IN];
__device__ __nv_bfloat16  g_Bo_hi[C_IN * V_DIM];
__device__ __nv_bfloat16  g_Bo_lo[C_IN * V_DIM];
__device__ __nv_bfloat16  g_fhi  [BATCH * SEQ_K * D_DIM];
__device__ __nv_bfloat16  g_flo  [BATCH * SEQ_K * D_DIM];
__device__ __nv_bfloat16  g_gth  [BATCH * V_DIM * SEQ_K];
__device__ __nv_bfloat16  g_gtl  [BATCH * V_DIM * SEQ_K];

// ================= baseline-ISA helpers =================
__device__ __forceinline__ uint32_t smem_u32(const void* p) {
    uint32_t a;
    asm("{ .reg .u64 t; cvta.to.shared.u64 t, %1; cvt.u32.u64 %0, t; }" : "=r"(a) : "l"(p));
    return a;
}
__device__ __forceinline__ float ex2f(float x) {
    float y; asm("ex2.approx.f32 %0, %1;" : "=f"(y) : "f"(x)); return y;
}
#define CP_ASYNC16(dst, src) \
    asm volatile("cp.async.cg.shared.global [%0], [%1], 16;" :: "r"(dst), "l"(src))
#define CP_COMMIT() asm volatile("cp.async.commit_group;" ::: "memory")
#define CP_WAIT(N)  asm volatile("cp.async.wait_group %0;" :: "n"(N) : "memory")
#define LDSM_X4(r0, r1, r2, r3, addr) \
    asm volatile("ldmatrix.sync.aligned.m8n8.x4.shared.b16 {%0,%1,%2,%3}, [%4];" \
                 : "=r"(r0), "=r"(r1), "=r"(r2), "=r"(r3) : "r"(addr))
#define MMA16816(d, a, b0v, b1v) \
    asm volatile("mma.sync.aligned.m16n8k16.row.col.f32.bf16.bf16.f32 " \
                 "{%0,%1,%2,%3}, {%4,%5,%6,%7}, {%8,%9}, {%0,%1,%2,%3};" \
                 : "+f"((d)[0]), "+f"((d)[1]), "+f"((d)[2]), "+f"((d)[3]) \
                 : "r"((a)[0]), "r"((a)[1]), "r"((a)[2]), "r"((a)[3]), \
                   "r"(b0v), "r"(b1v))

// ================= conversion / packing =================
__global__ void convert_x_k(const float* __restrict__ x,
                            __nv_bfloat16* __restrict__ xhi, __nv_bfloat16* __restrict__ xlo)
{
    size_t i = ((size_t)blockIdx.x * blockDim.x + threadIdx.x) * 8;
    if (i >= (size_t)M_ROWS * C_IN) return;
    float4 a = *(const float4*)(x + i);
    float4 b = *(const float4*)(x + i + 4);
    float v[8] = {a.x, a.y, a.z, a.w, b.x, b.y, b.z, b.w};
    __nv_bfloat16 h[8], l[8];
    #pragma unroll
    for (int j = 0; j < 8; j++) {
        h[j] = __float2bfloat16(v[j]);
        l[j] = __float2bfloat16(v[j] - __bfloat162float(h[j]));
    }
    *(uint4*)(xhi + i) = *(const uint4*)h;
    *(uint4*)(xlo + i) = *(const uint4*)l;
}

__global__ void pack_proj_k(const float* __restrict__ Wt, const float* __restrict__ Wp,
                            const float* __restrict__ Wg,
                            __nv_bfloat16* __restrict__ bhi, __nv_bfloat16* __restrict__ blo)
{
    int i = blockIdx.x * blockDim.x + threadIdx.x;
    if (i >= NPROJ * C_IN) return;
    int n = i / C_IN, k = i % C_IN;
    float v;
    if (n < 64)       v = Wt[k * 64 + n];
    else if (n < 128) v = Wp[k * 64 + (n - 64)];
    else              v = Wg[k * 256 + (n - 128)];
    __nv_bfloat16 h = __float2bfloat16(v);
    bhi[i] = h;
    blo[i] = __float2bfloat16(v - __bfloat162float(h));
}

__global__ void pack_wo_k(const float* __restrict__ Wo,
                          __nv_bfloat16* __restrict__ bhi, __nv_bfloat16* __restrict__ blo)
{
    int i = blockIdx.x * blockDim.x + threadIdx.x;
    if (i >= C_IN * V_DIM) return;
    int n = i / V_DIM, k = i % V_DIM;
    float v = Wo[k * C_IN + n];
    __nv_bfloat16 h = __float2bfloat16(v);
    bhi[i] = h;
    blo[i] = __float2bfloat16(v - __bfloat162float(h));
}

// ================= mma.sync split-bf16 GEMM: 256x128x32, 4-stage, warp 64x64 =================
// C[M, ldc](n-block) = A @ B^T; 3 terms via K-region loop [AhiBhi, AloBhi, AhiBlo].
#define BK      32
#define ASTRIDE 40      // padded bf16 row stride (80 B)
#define STAGES  4
#define GEMM_SA_ELEMS (256 * ASTRIDE)           // per stage
#define GEMM_SB_ELEMS (128 * ASTRIDE)
#define GEMM_SMEM_BYTES (STAGES * (GEMM_SA_ELEMS + GEMM_SB_ELEMS) * 2)  // 122880

template <int KB>
__global__ __launch_bounds__(256, 1) void gemm_mma(
    const __nv_bfloat16* __restrict__ Ahi, const __nv_bfloat16* __restrict__ Alo,
    const __nv_bfloat16* __restrict__ Bhi, const __nv_bfloat16* __restrict__ Blo,
    float* __restrict__ C, int ldc,
    const float* __restrict__ res, const float* __restrict__ gammaP)
{
    extern __shared__ __nv_bfloat16 sg[];
    const uint32_t sAb = smem_u32(sg);                                  // stages of A
    const uint32_t sBb = sAb + STAGES * GEMM_SA_ELEMS * 2;              // stages of B

    const int tid  = threadIdx.x;
    const int lane = tid & 31;
    const int wid  = tid >> 5;
    const int warpM = wid & 3;      // 0..3 -> 64 rows each (256 total)
    const int warpN = wid >> 2;     // 0..1 -> 64 cols each (128 total)
    const int m0 = blockIdx.y * 256;
    const int n0 = blockIdx.x * 128;

    constexpr int KPC = KB / BK;
    constexpr int CHUNKS = 3 * KPC;

    auto load_chunk = [&](int c, int stg) {
        const int reg  = c / KPC;
        const int kcol = (c - reg * KPC) * BK;
        const __nv_bfloat16* As = (reg == 1) ? Alo : Ahi;
        const __nv_bfloat16* Bs = (reg == 2) ? Blo : Bhi;
        const uint32_t aB = sAb + stg * GEMM_SA_ELEMS * 2;
        const uint32_t bB = sBb + stg * GEMM_SB_ELEMS * 2;
        #pragma unroll
        for (int it = 0; it < 4; it++) {               // A: 256 rows x 4 x 16B
            int idx = tid + it * 256;
            int row = idx >> 2, c16 = idx & 3;
            CP_ASYNC16(aB + (row * ASTRIDE + c16 * 8) * 2,
                       As + (size_t)(m0 + row) * KB + kcol + c16 * 8);
        }
        #pragma unroll
        for (int it = 0; it < 2; it++) {               // B: 128 rows x 4 x 16B
            int idx = tid + it * 256;
            int row = idx >> 2, c16 = idx & 3;
            CP_ASYNC16(bB + (row * ASTRIDE + c16 * 8) * 2,
                       Bs + (size_t)(n0 + row) * KB + kcol + c16 * 8);
        }
        CP_COMMIT();
    };

    float acc[4][8][4];
    #pragma unroll
    for (int i = 0; i < 4; i++)
        #pragma unroll
        for (int j = 0; j < 8; j++)
            #pragma unroll
            for (int r = 0; r < 4; r++) acc[i][j][r] = 0.f;

    // prologue: fill STAGES-1 stages
    #pragma unroll
    for (int s = 0; s < STAGES - 1; s++) load_chunk(s, s);

    for (int c = 0; c < CHUNKS; c++) {
        CP_WAIT(STAGES - 2);     // chunk c arrived (this thread)
        __syncthreads();         // all threads' chunk c visible; slot (c-1)%4 consumers done

        const int stg = c & (STAGES - 1);
        const uint32_t aB = sAb + stg * GEMM_SA_ELEMS * 2;
        const uint32_t bB = sBb + stg * GEMM_SB_ELEMS * 2;
        #pragma unroll
        for (int k0 = 0; k0 < BK; k0 += 16) {
            uint32_t af[4][4];
            #pragma unroll
            for (int i = 0; i < 4; i++) {
                uint32_t addr = aB +
                    ((warpM * 64 + i * 16 + (lane & 15)) * ASTRIDE + k0 + (lane >> 4) * 8) * 2;
                LDSM_X4(af[i][0], af[i][1], af[i][2], af[i][3], addr);
            }
            uint32_t bf[4][4];
            int g = lane >> 3, rr = lane & 7;
            #pragma unroll
            for (int j2 = 0; j2 < 4; j2++) {
                uint32_t addr = bB +
                    ((warpN * 64 + j2 * 16 + (g & 2) * 4 + rr) * ASTRIDE + k0 + (g & 1) * 8) * 2;
                LDSM_X4(bf[j2][0], bf[j2][1], bf[j2][2], bf[j2][3], addr);
            }
            #pragma unroll
            for (int i = 0; i < 4; i++)
                #pragma unroll
                for (int j = 0; j < 8; j++)
                    MMA16816(acc[i][j], af[i], bf[j >> 1][(j & 1) * 2], bf[j >> 1][(j & 1) * 2 + 1]);
        }
        if (c + STAGES - 1 < CHUNKS) load_chunk(c + STAGES - 1, (c + STAGES - 1) & (STAGES - 1));
        else CP_COMMIT();        // keep group count in step
    }

    // epilogue
    const float gamma = res ? *gammaP : 0.f;
    #pragma unroll
    for (int i = 0; i < 4; i++) {
        #pragma unroll
        for (int j = 0; j < 8; j++) {
            int gr = m0 + warpM * 64 + i * 16 + (lane >> 2);
            int gc = n0 + warpN * 64 + j * 8 + (lane & 3) * 2;
            size_t off0 = (size_t)gr * ldc + gc;
            size_t off1 = off0 + (size_t)8 * ldc;
            if (res) {
                float2 r0 = *(const float2*)(res + off0);
                float2 r1 = *(const float2*)(res + off1);
                float2 o0, o1;
                o0.x = fmaf(gamma, acc[i][j][0], r0.x);
                o0.y = fmaf(gamma, acc[i][j][1], r0.y);
                o1.x = fmaf(gamma, acc[i][j][2], r1.x);
                o1.y = fmaf(gamma, acc[i][j][3], r1.y);
                *(float2*)(C + off0) = o0;
                *(float2*)(C + off1) = o1;
            } else {
                *(float2*)(C + off0) = make_float2(acc[i][j][0], acc[i][j][1]);
                *(float2*)(C + off1) = make_float2(acc[i][j][2], acc[i][j][3]);
            }
        }
    }
}

// ---------------- 2x2 maxpool ----------------
__global__ void pool_k(const float* __restrict__ proj,
                       float* __restrict__ phiP, float* __restrict__ gP)
{
    const int NPHI4 = BATCH * SEQ_K * (D_DIM / 4);
    const int NG4   = BATCH * SEQ_K * (V_DIM / 4);
    int i = blockIdx.x * blockDim.x + threadIdx.x;
    if (i < NPHI4) {
        int bp = i >> 4, c4 = i & 15;
        int b = bp >> 10, ij = bp & 1023, ii = ij >> 5, jj = ij & 31;
        int r = b * 4096 + ii * 128 + jj * 2;
        const float* base = proj + 64 + (size_t)c4 * 4;
        float4 v0 = *(const float4*)(base + (size_t)r * NPROJ);
        float4 v1 = *(const float4*)(base + (size_t)(r + 1) * NPROJ);
        float4 v2 = *(const float4*)(base + (size_t)(r + 64) * NPROJ);
        float4 v3 = *(const float4*)(base + (size_t)(r + 65) * NPROJ);
        float4 o;
        o.x = fmaxf(fmaxf(v0.x, v1.x), fmaxf(v2.x, v3.x));
        o.y = fmaxf(fmaxf(v0.y, v1.y), fmaxf(v2.y, v3.y));
        o.z = fmaxf(fmaxf(v0.z, v1.z), fmaxf(v2.z, v3.z));
        o.w = fmaxf(fmaxf(v0.w, v1.w), fmaxf(v2.w, v3.w));
        *((float4*)(phiP + (size_t)bp * 64) + c4) = o;
    } else {
        int j = i - NPHI4;
        if (j < NG4) {
            int bp = j >> 6, c4 = j & 63;
            int b = bp >> 10, ij = bp & 1023, ii = ij >> 5, jj = ij & 31;
            int r = b * 4096 + ii * 128 + jj * 2;
            const float* base = proj + 128 + (size_t)c4 * 4;
            float4 v0 = *(const float4*)(base + (size_t)r * NPROJ);
            float4 v1 = *(const float4*)(base + (size_t)(r + 1) * NPROJ);
            float4 v2 = *(const float4*)(base + (size_t)(r + 64) * NPROJ);
            float4 v3 = *(const float4*)(base + (size_t)(r + 65) * NPROJ);
            float4 o;
            o.x = fmaxf(fmaxf(v0.x, v1.x), fmaxf(v2.x, v3.x));
            o.y = fmaxf(fmaxf(v0.y, v1.y), fmaxf(v2.y, v3.y));
            o.z = fmaxf(fmaxf(v0.z, v1.z), fmaxf(v2.z, v3.z));
            o.w = fmaxf(fmaxf(v0.w, v1.w), fmaxf(v2.w, v3.w));
            *((float4*)(gP + (size_t)bp * 256) + c4) = o;
        }
    }
}

// ---------------- split phi fp32 -> bf16 hi/lo ----------------
__global__ void split_phi_k(const float* __restrict__ phiP,
                            __nv_bfloat16* __restrict__ fhi, __nv_bfloat16* __restrict__ flo)
{
    size_t i = ((size_t)blockIdx.x * blockDim.x + threadIdx.x) * 4;
    if (i >= (size_t)BATCH * SEQ_K * D_DIM) return;
    float4 v = *(const float4*)(phiP + i);
    float f[4] = {v.x, v.y, v.z, v.w};
    __nv_bfloat16 h[4], l[4];
    #pragma unroll
    for (int j = 0; j < 4; j++) {
        h[j] = __float2bfloat16(f[j]);
        l[j] = __float2bfloat16(f[j] - __bfloat162float(h[j]));
    }
    *(uint2*)(fhi + i) = *(const uint2*)h;
    *(uint2*)(flo + i) = *(const uint2*)l;
}

// ---------------- transpose+split g ----------------
__global__ void transT_g_k(const float* __restrict__ gP,
                           __nv_bfloat16* __restrict__ gth, __nv_bfloat16* __restrict__ gtl)
{
    __shared__ float sm[32][33];
    const int t = threadIdx.x;
    const int v0 = blockIdx.x * 32;
    const int k0 = blockIdx.y * 32;
    const int b  = blockIdx.z;
    {
        int r = t >> 3, cg = t & 7;
        float4 v = *(const float4*)(gP + (size_t)(b * SEQ_K + k0 + r) * V_DIM + v0 + cg * 4);
        sm[r][cg * 4 + 0] = v.x; sm[r][cg * 4 + 1] = v.y;
        sm[r][cg * 4 + 2] = v.z; sm[r][cg * 4 + 3] = v.w;
    }
    __syncthreads();
    {
        int v = t >> 3, kg = t & 7;
        __nv_bfloat16 h[4], l[4];
        #pragma unroll
        for (int j = 0; j < 4; j++) {
            float f = sm[kg * 4 + j][v];
            h[j] = __float2bfloat16(f);
            l[j] = __float2bfloat16(f - __bfloat162float(h[j]));
        }
        size_t off = (size_t)(b * V_DIM + v0 + v) * SEQ_K + k0 + kg * 4;
        *(uint2*)(gth + off) = *(const uint2*)h;
        *(uint2*)(gtl + off) = *(const uint2*)l;
    }
}

// ================= flash attention on mma.sync (split-bf16) — unchanged from R6 =================
#define OFF_TH  0u
#define OFF_TL  9216u
#define OFF_FH  18432u
#define OFF_FL  23040u
#define OFF_GH  27648u
#define OFF_GL  46080u
#define OFF_SPH 64512u
#define OFF_SPL 73728u
#define ATTN_BF16_ELEMS 82944u
#define ATTN_SMEM_BYTES (82944 * 2 + 2 * 512 * 4)

__global__ __launch_bounds__(512, 1) void attn_k(
    const float* __restrict__ proj,
    const __nv_bfloat16* __restrict__ fhi, const __nv_bfloat16* __restrict__ flo,
    const __nv_bfloat16* __restrict__ gth, const __nv_bfloat16* __restrict__ gtl,
    __nv_bfloat16* __restrict__ thi, __nv_bfloat16* __restrict__ tlo)
{
    extern __shared__ __nv_bfloat16 sb[];
    float* redA = (float*)(sb + ATTN_BF16_ELEMS);
    float* redB = redA + 512;

    const uint32_t sb32 = smem_u32(sb);
    const int tid  = threadIdx.x;
    const int lane = tid & 31;
    const int wid  = tid >> 5;
    const int warpM = wid >> 2;
    const int warpN = wid & 3;
    const int b  = blockIdx.y;
    const int qt = blockIdx.x;
    const int qbase = b * SEQ_Q + qt * 128;
    const float L2E = 1.4426950408889634f;

    #pragma unroll
    for (int i = tid; i < 128 * 16; i += 512) {
        int q = i >> 4, c4 = i & 15;
        float4 v = *(const float4*)(proj + (size_t)(qbase + q) * NPROJ + c4 * 4);
        float f[4] = {v.x * L2E, v.y * L2E, v.z * L2E, v.w * L2E};
        __nv_bfloat16 h[4], l[4];
        #pragma unroll
        for (int j = 0; j < 4; j++) {
            h[j] = __float2bfloat16(f[j]);
            l[j] = __float2bfloat16(f[j] - __bfloat162float(h[j]));
        }
        uint32_t o = q * 72 + c4 * 4;
        *(uint2*)(sb + OFF_TH + o) = *(const uint2*)h;
        *(uint2*)(sb + OFF_TL + o) = *(const uint2*)l;
    }
    __syncthreads();

    float acc[2][8][4];
    float m[2][2], l[2][2];
    #pragma unroll
    for (int mf = 0; mf < 2; mf++) {
        m[mf][0] = -1e30f; m[mf][1] = -1e30f;
        l[mf][0] = 0.f;    l[mf][1] = 0.f;
        #pragma unroll
        for (int nf = 0; nf < 8; nf++)
            #pragma unroll
            for (int c = 0; c < 4; c++) acc[mf][nf][c] = 0.f;
    }

    const int rowA = warpM * 32 + (lane & 15);
    const int rq   = lane >> 2;
    const int cq2  = (lane & 3) * 2;

    for (int kt = 0; kt < 16; kt++) {
        __syncthreads();
        {
            const size_t fb = (size_t)(b * SEQ_K + kt * 64) * 64;
            #pragma unroll
            for (int i = 0; i < 2; i++) {
                int id = tid + i * 512;
                int half = id >> 9, j = id & 511;
                int row = j >> 3, c = j & 7;
                CP_ASYNC16(sb32 + ((half ? OFF_FL : OFF_FH) + row * 72 + c * 8) * 2,
                           (half ? flo : fhi) + fb + (size_t)row * 64 + c * 8);
            }
            CP_COMMIT();
            const size_t gb = (size_t)b * V_DIM * SEQ_K + kt * 64;
            #pragma unroll
            for (int i = 0; i < 8; i++) {
                int id = tid + i * 512;
                int half = id >> 11, j = id & 2047;
                int v = j >> 3, c = j & 7;
                CP_ASYNC16(sb32 + ((half ? OFF_GL : OFF_GH) + v * 72 + c * 8) * 2,
                           (half ? gtl : gth) + gb + (size_t)v * SEQ_K + c * 8);
            }
            CP_COMMIT();
        }
        CP_WAIT(1);
        __syncthreads();

        float aq[2][2][4];
        #pragma unroll
        for (int mf = 0; mf < 2; mf++)
            #pragma unroll
            for (int nf = 0; nf < 2; nf++)
                #pragma unroll
                for (int c = 0; c < 4; c++) aq[mf][nf][c] = 0.f;

        #pragma unroll
        for (int reg = 0; reg < 3; reg++) {
            const uint32_t aoff = (reg == 1) ? OFF_TL : OFF_TH;
            const uint32_t boff = (reg == 2) ? OFF_FL : OFF_FH;
            #pragma unroll
            for (int k0 = 0; k0 < 64; k0 += 16) {
                uint32_t a0[4], a1[4], bb[4];
                uint32_t colA = k0 + (lane >> 4) * 8;
                LDSM_X4(a0[0], a0[1], a0[2], a0[3],
                        sb32 + (aoff + (rowA) * 72 + colA) * 2);
                LDSM_X4(a1[0], a1[1], a1[2], a1[3],
                        sb32 + (aoff + (rowA + 16) * 72 + colA) * 2);
                int g = lane >> 3, rr = lane & 7;
                LDSM_X4(bb[0], bb[1], bb[2], bb[3],
                        sb32 + (boff + (warpN * 16 + (g & 2) * 4 + rr) * 72 + k0 + (g & 1) * 8) * 2);
                MMA16816(aq[0][0], a0, bb[0], bb[1]);
                MMA16816(aq[0][1], a0, bb[2], bb[3]);
                MMA16816(aq[1][0], a1, bb[0], bb[1]);
                MMA16816(aq[1][1], a1, bb[2], bb[3]);
            }
        }

        float mx[2][2];
        #pragma unroll
        for (int mf = 0; mf < 2; mf++)
            #pragma unroll
            for (int h = 0; h < 2; h++) {
                float t = fmaxf(fmaxf(aq[mf][0][h * 2], aq[mf][0][h * 2 + 1]),
                                fmaxf(aq[mf][1][h * 2], aq[mf][1][h * 2 + 1]));
                t = fmaxf(t, __shfl_xor_sync(0xffffffffu, t, 1));
                t = fmaxf(t, __shfl_xor_sync(0xffffffffu, t, 2));
                mx[mf][h] = t;
            }
        if ((lane & 3) == 0) {
            #pragma unroll
            for (int mf = 0; mf < 2; mf++)
                #pragma unroll
                for (int h = 0; h < 2; h++)
                    redA[warpN * 128 + warpM * 32 + mf * 16 + h * 8 + rq] = mx[mf][h];
        }
        __syncthreads();

        float mnew[2][2], scale[2][2], rsum[2][2];
        #pragma unroll
        for (int mf = 0; mf < 2; mf++)
            #pragma unroll
            for (int h = 0; h < 2; h++) {
                int r = warpM * 32 + mf * 16 + h * 8 + rq;
                float v = m[mf][h];
                #pragma unroll
                for (int w = 0; w < 4; w++) v = fmaxf(v, redA[w * 128 + r]);
                mnew[mf][h] = v;
                rsum[mf][h] = 0.f;
            }

        #pragma unroll
        for (int mf = 0; mf < 2; mf++)
            #pragma unroll
            for (int nf = 0; nf < 2; nf++)
                #pragma unroll
                for (int h = 0; h < 2; h++) {
                    float p0 = ex2f(aq[mf][nf][h * 2]     - mnew[mf][h]);
                    float p1 = ex2f(aq[mf][nf][h * 2 + 1] - mnew[mf][h]);
                    rsum[mf][h] += p0 + p1;
                    __nv_bfloat16 h0 = __float2bfloat16(p0);
                    __nv_bfloat16 h1 = __float2bfloat16(p1);
                    __nv_bfloat16 l0 = __float2bfloat16(p0 - __bfloat162float(h0));
                    __nv_bfloat16 l1 = __float2bfloat16(p1 - __bfloat162float(h1));
                    int row = warpM * 32 + mf * 16 + h * 8 + rq;
                    int col = warpN * 16 + nf * 8 + cq2;
                    __nv_bfloat162 hv; hv.x = h0; hv.y = h1;
                    __nv_bfloat162 lv; lv.x = l0; lv.y = l1;
                    *(__nv_bfloat162*)(sb + OFF_SPH + row * 72 + col) = hv;
                    *(__nv_bfloat162*)(sb + OFF_SPL + row * 72 + col) = lv;
                }
        #pragma unroll
        for (int mf = 0; mf < 2; mf++)
            #pragma unroll
            for (int h = 0; h < 2; h++) {
                float t = rsum[mf][h];
                t += __shfl_xor_sync(0xffffffffu, t, 1);
                t += __shfl_xor_sync(0xffffffffu, t, 2);
                rsum[mf][h] = t;
                scale[mf][h] = ex2f(m[mf][h] - mnew[mf][h]);
                m[mf][h] = mnew[mf][h];
            }
        if ((lane & 3) == 0) {
            #pragma unroll
            for (int mf = 0; mf < 2; mf++)
                #pragma unroll
                for (int h = 0; h < 2; h++)
                    redB[warpN * 128 + warpM * 32 + mf * 16 + h * 8 + rq] = rsum[mf][h];
        }
        CP_WAIT(0);
        __syncthreads();

        #pragma unroll
        for (int mf = 0; mf < 2; mf++)
            #pragma unroll
            for (int h = 0; h < 2; h++) {
                int r = warpM * 32 + mf * 16 + h * 8 + rq;
                float s = 0.f;
                #pragma unroll
                for (int w = 0; w < 4; w++) s += redB[w * 128 + r];
                l[mf][h] = l[mf][h] * scale[mf][h] + s;
            }
        #pragma unroll
        for (int mf = 0; mf < 2; mf++)
            #pragma unroll
            for (int nf = 0; nf < 8; nf++) {
                acc[mf][nf][0] *= scale[mf][0];
                acc[mf][nf][1] *= scale[mf][0];
                acc[mf][nf][2] *= scale[mf][1];
                acc[mf][nf][3] *= scale[mf][1];
            }

        #pragma unroll
        for (int reg = 0; reg < 3; reg++) {
            const uint32_t aoff = (reg == 1) ? OFF_SPL : OFF_SPH;
            const uint32_t boff = (reg == 2) ? OFF_GL : OFF_GH;
            #pragma unroll
            for (int k0 = 0; k0 < 64; k0 += 16) {
                uint32_t a0[4], a1[4];
                uint32_t colA = k0 + (lane >> 4) * 8;
                LDSM_X4(a0[0], a0[1], a0[2], a0[3],
                        sb32 + (aoff + (rowA) * 72 + colA) * 2);
                LDSM_X4(a1[0], a1[1], a1[2], a1[3],
                        sb32 + (aoff + (rowA + 16) * 72 + colA) * 2);
                int g = lane >> 3, rr = lane & 7;
                #pragma unroll
                for (int j2 = 0; j2 < 4; j2++) {
                    uint32_t bb[4];
                    LDSM_X4(bb[0], bb[1], bb[2], bb[3],
                            sb32 + (boff + (warpN * 64 + j2 * 16 + (g & 2) * 4 + rr) * 72
                                    + k0 + (g & 1) * 8) * 2);
                    MMA16816(acc[0][j2 * 2 + 0], a0, bb[0], bb[1]);
                    MMA16816(acc[0][j2 * 2 + 1], a0, bb[2], bb[3]);
                    MMA16816(acc[1][j2 * 2 + 0], a1, bb[0], bb[1]);
                    MMA16816(acc[1][j2 * 2 + 1], a1, bb[2], bb[3]);
                }
            }
        }
    }

    #pragma unroll
    for (int mf = 0; mf < 2; mf++)
        #pragma unroll
        for (int h = 0; h < 2; h++) {
            float inv = 1.f / l[mf][h];
            int row = qbase + warpM * 32 + mf * 16 + h * 8 + rq;
            #pragma unroll
            for (int nf = 0; nf < 8; nf++) {
                int col = warpN * 64 + nf * 8 + cq2;
                float v0 = acc[mf][nf][h * 2]     * inv;
                float v1 = acc[mf][nf][h * 2 + 1] * inv;
                __nv_bfloat16 h0 = __float2bfloat16(v0);
                __nv_bfloat16 h1 = __float2bfloat16(v1);
                __nv_bfloat16 l0 = __float2bfloat16(v0 - __bfloat162float(h0));
                __nv_bfloat16 l1 = __float2bfloat16(v1 - __bfloat162float(h1));
                __nv_bfloat162 hv; hv.x = h0; hv.y = h1;
                __nv_bfloat162 lv; lv.x = l0; lv.y = l1;
                *(__nv_bfloat162*)(thi + (size_t)row * V_DIM + col) = hv;
                *(__nv_bfloat162*)(tlo + (size_t)row * V_DIM + col) = lv;
            }
        }
}

// ---------------- launch ----------------
extern "C" void kernel_launch(void* const* d_in, const int* in_sizes, int n_in,
                              void* d_out, int out_size)
{
    const float* x     = (const float*)d_in[0];
    const float* Wt    = (const float*)d_in[1];
    const float* Wp    = (const float*)d_in[2];
    const float* Wg    = (const float*)d_in[3];
    const float* Wo    = (const float*)d_in[4];
    const float* gamma = (const float*)d_in[5];
    float* out = (float*)d_out;

    float *proj, *phiP, *gP;
    __nv_bfloat16 *xhi, *xlo, *thi, *tlo, *Bph, *Bpl, *Boh, *Bol, *fhi, *flo, *gth, *gtl;
    cudaGetSymbolAddress((void**)&proj, g_proj);
    cudaGetSymbolAddress((void**)&phiP, g_phiP);
    cudaGetSymbolAddress((void**)&gP,   g_gP);
    cudaGetSymbolAddress((void**)&xhi,  g_xhi);
    cudaGetSymbolAddress((void**)&xlo,  g_xlo);
    cudaGetSymbolAddress((void**)&thi,  g_thi);
    cudaGetSymbolAddress((void**)&tlo,  g_tlo);
    cudaGetSymbolAddress((void**)&Bph,  g_Bp_hi);
    cudaGetSymbolAddress((void**)&Bpl,  g_Bp_lo);
    cudaGetSymbolAddress((void**)&Boh,  g_Bo_hi);
    cudaGetSymbolAddress((void**)&Bol,  g_Bo_lo);
    cudaGetSymbolAddress((void**)&fhi,  g_fhi);
    cudaGetSymbolAddress((void**)&flo,  g_flo);
    cudaGetSymbolAddress((void**)&gth,  g_gth);
    cudaGetSymbolAddress((void**)&gtl,  g_gtl);

    cudaFuncSetAttribute(gemm_mma<512>, cudaFuncAttributeMaxDynamicSharedMemorySize, GEMM_SMEM_BYTES);
    cudaFuncSetAttribute(gemm_mma<256>, cudaFuncAttributeMaxDynamicSharedMemorySize, GEMM_SMEM_BYTES);
    cudaFuncSetAttribute(attn_k, cudaFuncAttributeMaxDynamicSharedMemorySize, ATTN_SMEM_BYTES);

    // 1. split conversions / weight packs
    convert_x_k<<<(M_ROWS * C_IN / 8 + 255) / 256, 256>>>(x, xhi, xlo);
    pack_proj_k<<<(NPROJ * C_IN + 255) / 256, 256>>>(Wt, Wp, Wg, Bph, Bpl);
    pack_wo_k<<<(C_IN * V_DIM + 255) / 256, 256>>>(Wo, Boh, Bol);
    // 2. fused projection (mma.sync): proj = x @ [Wt|Wp|Wg]
    gemm_mma<512><<<dim3(NPROJ / 128, M_ROWS / 256), 256, GEMM_SMEM_BYTES>>>(
        xhi, xlo, Bph, Bpl, proj, NPROJ, nullptr, nullptr);
    // 3. 2x2 maxpool then split/transpose
    {
        int total = BATCH * SEQ_K * (D_DIM / 4) + BATCH * SEQ_K * (V_DIM / 4);
        pool_k<<<(total + 255) / 256, 256>>>(proj, phiP, gP);
    }
    split_phi_k<<<(BATCH * SEQ_K * D_DIM / 4 + 255) / 256, 256>>>(phiP, fhi, flo);
    transT_g_k<<<dim3(V_DIM / 32, SEQ_K / 32, BATCH), 256>>>(gP, gth, gtl);
    // 4. flash attention on mma.sync
    attn_k<<<dim3(SEQ_Q / 128, BATCH), 512, ATTN_SMEM_BYTES>>>(
        proj, fhi, flo, gth, gtl, thi, tlo);
    // 5. output projection (mma.sync) + residual
    gemm_mma<256><<<dim3(C_IN / 128, M_ROWS / 256), 256, GEMM_SMEM_BYTES>>>(
        thi, tlo, Boh, Bol, out, C_IN, x, gamma);
}

// round 8
// speedup vs baseline: 6.0839x; 1.2136x over previous
#include <cuda_runtime.h>
#include <cuda_bf16.h>
#include <math.h>
#include <cstdint>

// x: [16, 64, 64, 512] -> rows M = 65536, C = 512
#define M_ROWS 65536
#define C_IN   512
#define D_DIM  64
#define V_DIM  256
#define BATCH  16
#define SEQ_Q  4096
#define SEQ_K  1024
#define NPROJ  384   // 64 theta | 64 phi | 256 g

// ---------------- scratch (device globals; no allocation allowed) ----------------
__device__ float          g_proj [M_ROWS * NPROJ];
__device__ float          g_gP   [BATCH * SEQ_K * V_DIM];
__device__ __nv_bfloat16  g_xhi  [M_ROWS * C_IN];
__device__ __nv_bfloat16  g_xlo  [M_ROWS * C_IN];
__device__ __nv_bfloat16  g_thi  [M_ROWS * V_DIM];
__device__ __nv_bfloat16  g_tlo  [M_ROWS * V_DIM];
__device__ __nv_bfloat16  g_Bp_hi[NPROJ * C_IN];
__device__ __nv_bfloat16  g_Bp_lo[NPROJ * C_IN];
__device__ __nv_bfloat16  g_Bo_hi[C_IN * V_DIM];
__device__ __nv_bfloat16  g_Bo_lo[C_IN * V_DIM];
__device__ __nv_bfloat16  g_fhi  [BATCH * SEQ_K * D_DIM];
__device__ __nv_bfloat16  g_flo  [BATCH * SEQ_K * D_DIM];
__device__ __nv_bfloat16  g_gth  [BATCH * V_DIM * SEQ_K];
__device__ __nv_bfloat16  g_gtl  [BATCH * V_DIM * SEQ_K];

// ================= baseline-ISA helpers =================
__device__ __forceinline__ uint32_t smem_u32(const void* p) {
    uint32_t a;
    asm("{ .reg .u64 t; cvta.to.shared.u64 t, %1; cvt.u32.u64 %0, t; }" : "=r"(a) : "l"(p));
    return a;
}
__device__ __forceinline__ float ex2f(float x) {
    float y; asm("ex2.approx.f32 %0, %1;" : "=f"(y) : "f"(x)); return y;
}
#define CP_ASYNC16(dst, src) \
    asm volatile("cp.async.cg.shared.global [%0], [%1], 16;" :: "r"(dst), "l"(src))
#define CP_COMMIT() asm volatile("cp.async.commit_group;" ::: "memory")
#define CP_WAIT(N)  asm volatile("cp.async.wait_group %0;" :: "n"(N) : "memory")
#define LDSM_X4(r0, r1, r2, r3, addr) \
    asm volatile("ldmatrix.sync.aligned.m8n8.x4.shared.b16 {%0,%1,%2,%3}, [%4];" \
                 : "=r"(r0), "=r"(r1), "=r"(r2), "=r"(r3) : "r"(addr))
#define MMA16816(d, a, b0v, b1v) \
    asm volatile("mma.sync.aligned.m16n8k16.row.col.f32.bf16.bf16.f32 " \
                 "{%0,%1,%2,%3}, {%4,%5,%6,%7}, {%8,%9}, {%0,%1,%2,%3};" \
                 : "+f"((d)[0]), "+f"((d)[1]), "+f"((d)[2]), "+f"((d)[3]) \
                 : "r"((a)[0]), "r"((a)[1]), "r"((a)[2]), "r"((a)[3]), \
                   "r"(b0v), "r"(b1v))

// ================= conversion / packing =================
__global__ void convert_x_k(const float* __restrict__ x,
                            __nv_bfloat16* __restrict__ xhi, __nv_bfloat16* __restrict__ xlo)
{
    size_t i = ((size_t)blockIdx.x * blockDim.x + threadIdx.x) * 8;
    if (i >= (size_t)M_ROWS * C_IN) return;
    float4 a = *(const float4*)(x + i);
    float4 b = *(const float4*)(x + i + 4);
    float v[8] = {a.x, a.y, a.z, a.w, b.x, b.y, b.z, b.w};
    __nv_bfloat16 h[8], l[8];
    #pragma unroll
    for (int j = 0; j < 8; j++) {
        h[j] = __float2bfloat16(v[j]);
        l[j] = __float2bfloat16(v[j] - __bfloat162float(h[j]));
    }
    *(uint4*)(xhi + i) = *(const uint4*)h;
    *(uint4*)(xlo + i) = *(const uint4*)l;
}

__global__ void pack_proj_k(const float* __restrict__ Wt, const float* __restrict__ Wp,
                            const float* __restrict__ Wg,
                            __nv_bfloat16* __restrict__ bhi, __nv_bfloat16* __restrict__ blo)
{
    int i = blockIdx.x * blockDim.x + threadIdx.x;
    if (i >= NPROJ * C_IN) return;
    int n = i / C_IN, k = i % C_IN;
    float v;
    if (n < 64)       v = Wt[k * 64 + n];
    else if (n < 128) v = Wp[k * 64 + (n - 64)];
    else              v = Wg[k * 256 + (n - 128)];
    __nv_bfloat16 h = __float2bfloat16(v);
    bhi[i] = h;
    blo[i] = __float2bfloat16(v - __bfloat162float(h));
}

__global__ void pack_wo_k(const float* __restrict__ Wo,
                          __nv_bfloat16* __restrict__ bhi, __nv_bfloat16* __restrict__ blo)
{
    int i = blockIdx.x * blockDim.x + threadIdx.x;
    if (i >= C_IN * V_DIM) return;
    int n = i / V_DIM, k = i % V_DIM;
    float v = Wo[k * C_IN + n];
    __nv_bfloat16 h = __float2bfloat16(v);
    bhi[i] = h;
    blo[i] = __float2bfloat16(v - __bfloat162float(h));
}

// ================= mma.sync split-bf16 GEMM: 256x128x32, 4-stage, warp 64x64 =================
#define BK      32
#define ASTRIDE 40
#define STAGES  4
#define GEMM_SA_ELEMS (256 * ASTRIDE)
#define GEMM_SB_ELEMS (128 * ASTRIDE)
#define GEMM_SMEM_BYTES (STAGES * (GEMM_SA_ELEMS + GEMM_SB_ELEMS) * 2)

template <int KB>
__global__ __launch_bounds__(256, 1) void gemm_mma(
    const __nv_bfloat16* __restrict__ Ahi, const __nv_bfloat16* __restrict__ Alo,
    const __nv_bfloat16* __restrict__ Bhi, const __nv_bfloat16* __restrict__ Blo,
    float* __restrict__ C, int ldc,
    const float* __restrict__ res, const float* __restrict__ gammaP)
{
    extern __shared__ __nv_bfloat16 sg[];
    const uint32_t sAb = smem_u32(sg);
    const uint32_t sBb = sAb + STAGES * GEMM_SA_ELEMS * 2;

    const int tid  = threadIdx.x;
    const int lane = tid & 31;
    const int wid  = tid >> 5;
    const int warpM = wid & 3;
    const int warpN = wid >> 2;
    const int m0 = blockIdx.y * 256;
    const int n0 = blockIdx.x * 128;

    constexpr int KPC = KB / BK;
    constexpr int CHUNKS = 3 * KPC;

    auto load_chunk = [&](int c, int stg) {
        const int reg  = c / KPC;
        const int kcol = (c - reg * KPC) * BK;
        const __nv_bfloat16* As = (reg == 1) ? Alo : Ahi;
        const __nv_bfloat16* Bs = (reg == 2) ? Blo : Bhi;
        const uint32_t aB = sAb + stg * GEMM_SA_ELEMS * 2;
        const uint32_t bB = sBb + stg * GEMM_SB_ELEMS * 2;
        #pragma unroll
        for (int it = 0; it < 4; it++) {
            int idx = tid + it * 256;
            int row = idx >> 2, c16 = idx & 3;
            CP_ASYNC16(aB + (row * ASTRIDE + c16 * 8) * 2,
                       As + (size_t)(m0 + row) * KB + kcol + c16 * 8);
        }
        #pragma unroll
        for (int it = 0; it < 2; it++) {
            int idx = tid + it * 256;
            int row = idx >> 2, c16 = idx & 3;
            CP_ASYNC16(bB + (row * ASTRIDE + c16 * 8) * 2,
                       Bs + (size_t)(n0 + row) * KB + kcol + c16 * 8);
        }
        CP_COMMIT();
    };

    float acc[4][8][4];
    #pragma unroll
    for (int i = 0; i < 4; i++)
        #pragma unroll
        for (int j = 0; j < 8; j++)
            #pragma unroll
            for (int r = 0; r < 4; r++) acc[i][j][r] = 0.f;

    #pragma unroll
    for (int s = 0; s < STAGES - 1; s++) load_chunk(s, s);

    for (int c = 0; c < CHUNKS; c++) {
        CP_WAIT(STAGES - 2);
        __syncthreads();

        const int stg = c & (STAGES - 1);
        const uint32_t aB = sAb + stg * GEMM_SA_ELEMS * 2;
        const uint32_t bB = sBb + stg * GEMM_SB_ELEMS * 2;
        #pragma unroll
        for (int k0 = 0; k0 < BK; k0 += 16) {
            uint32_t af[4][4];
            #pragma unroll
            for (int i = 0; i < 4; i++) {
                uint32_t addr = aB +
                    ((warpM * 64 + i * 16 + (lane & 15)) * ASTRIDE + k0 + (lane >> 4) * 8) * 2;
                LDSM_X4(af[i][0], af[i][1], af[i][2], af[i][3], addr);
            }
            uint32_t bf[4][4];
            int g = lane >> 3, rr = lane & 7;
            #pragma unroll
            for (int j2 = 0; j2 < 4; j2++) {
                uint32_t addr = bB +
                    ((warpN * 64 + j2 * 16 + (g & 2) * 4 + rr) * ASTRIDE + k0 + (g & 1) * 8) * 2;
                LDSM_X4(bf[j2][0], bf[j2][1], bf[j2][2], bf[j2][3], addr);
            }
            #pragma unroll
            for (int i = 0; i < 4; i++)
                #pragma unroll
                for (int j = 0; j < 8; j++)
                    MMA16816(acc[i][j], af[i], bf[j >> 1][(j & 1) * 2], bf[j >> 1][(j & 1) * 2 + 1]);
        }
        if (c + STAGES - 1 < CHUNKS) load_chunk(c + STAGES - 1, (c + STAGES - 1) & (STAGES - 1));
        else CP_COMMIT();
    }

    const float gamma = res ? *gammaP : 0.f;
    #pragma unroll
    for (int i = 0; i < 4; i++) {
        #pragma unroll
        for (int j = 0; j < 8; j++) {
            int gr = m0 + warpM * 64 + i * 16 + (lane >> 2);
            int gc = n0 + warpN * 64 + j * 8 + (lane & 3) * 2;
            size_t off0 = (size_t)gr * ldc + gc;
            size_t off1 = off0 + (size_t)8 * ldc;
            if (res) {
                float2 r0 = *(const float2*)(res + off0);
                float2 r1 = *(const float2*)(res + off1);
                float2 o0, o1;
                o0.x = fmaf(gamma, acc[i][j][0], r0.x);
                o0.y = fmaf(gamma, acc[i][j][1], r0.y);
                o1.x = fmaf(gamma, acc[i][j][2], r1.x);
                o1.y = fmaf(gamma, acc[i][j][3], r1.y);
                *(float2*)(C + off0) = o0;
                *(float2*)(C + off1) = o1;
            } else {
                *(float2*)(C + off0) = make_float2(acc[i][j][0], acc[i][j][1]);
                *(float2*)(C + off1) = make_float2(acc[i][j][2], acc[i][j][3]);
            }
        }
    }
}

// ---------------- 2x2 maxpool: phi -> bf16 hi/lo directly; g -> fp32 ----------------
__global__ void pool_k(const float* __restrict__ proj,
                       __nv_bfloat16* __restrict__ fhi, __nv_bfloat16* __restrict__ flo,
                       float* __restrict__ gP)
{
    const int NPHI4 = BATCH * SEQ_K * (D_DIM / 4);
    const int NG4   = BATCH * SEQ_K * (V_DIM / 4);
    int i = blockIdx.x * blockDim.x + threadIdx.x;
    if (i < NPHI4) {
        int bp = i >> 4, c4 = i & 15;
        int b = bp >> 10, ij = bp & 1023, ii = ij >> 5, jj = ij & 31;
        int r = b * 4096 + ii * 128 + jj * 2;
        const float* base = proj + 64 + (size_t)c4 * 4;
        float4 v0 = *(const float4*)(base + (size_t)r * NPROJ);
        float4 v1 = *(const float4*)(base + (size_t)(r + 1) * NPROJ);
        float4 v2 = *(const float4*)(base + (size_t)(r + 64) * NPROJ);
        float4 v3 = *(const float4*)(base + (size_t)(r + 65) * NPROJ);
        float f[4];
        f[0] = fmaxf(fmaxf(v0.x, v1.x), fmaxf(v2.x, v3.x));
        f[1] = fmaxf(fmaxf(v0.y, v1.y), fmaxf(v2.y, v3.y));
        f[2] = fmaxf(fmaxf(v0.z, v1.z), fmaxf(v2.z, v3.z));
        f[3] = fmaxf(fmaxf(v0.w, v1.w), fmaxf(v2.w, v3.w));
        __nv_bfloat16 h[4], l[4];
        #pragma unroll
        for (int j = 0; j < 4; j++) {
            h[j] = __float2bfloat16(f[j]);
            l[j] = __float2bfloat16(f[j] - __bfloat162float(h[j]));
        }
        size_t off = (size_t)bp * 64 + c4 * 4;
        *(uint2*)(fhi + off) = *(const uint2*)h;
        *(uint2*)(flo + off) = *(const uint2*)l;
    } else {
        int j = i - NPHI4;
        if (j < NG4) {
            int bp = j >> 6, c4 = j & 63;
            int b = bp >> 10, ij = bp & 1023, ii = ij >> 5, jj = ij & 31;
            int r = b * 4096 + ii * 128 + jj * 2;
            const float* base = proj + 128 + (size_t)c4 * 4;
            float4 v0 = *(const float4*)(base + (size_t)r * NPROJ);
            float4 v1 = *(const float4*)(base + (size_t)(r + 1) * NPROJ);
            float4 v2 = *(const float4*)(base + (size_t)(r + 64) * NPROJ);
            float4 v3 = *(const float4*)(base + (size_t)(r + 65) * NPROJ);
            float4 o;
            o.x = fmaxf(fmaxf(v0.x, v1.x), fmaxf(v2.x, v3.x));
            o.y = fmaxf(fmaxf(v0.y, v1.y), fmaxf(v2.y, v3.y));
            o.z = fmaxf(fmaxf(v0.z, v1.z), fmaxf(v2.z, v3.z));
            o.w = fmaxf(fmaxf(v0.w, v1.w), fmaxf(v2.w, v3.w));
            *((float4*)(gP + (size_t)bp * 256) + c4) = o;
        }
    }
}

// ---------------- transpose+split g ----------------
__global__ void transT_g_k(const float* __restrict__ gP,
                           __nv_bfloat16* __restrict__ gth, __nv_bfloat16* __restrict__ gtl)
{
    __shared__ float sm[32][33];
    const int t = threadIdx.x;
    const int v0 = blockIdx.x * 32;
    const int k0 = blockIdx.y * 32;
    const int b  = blockIdx.z;
    {
        int r = t >> 3, cg = t & 7;
        float4 v = *(const float4*)(gP + (size_t)(b * SEQ_K + k0 + r) * V_DIM + v0 + cg * 4);
        sm[r][cg * 4 + 0] = v.x; sm[r][cg * 4 + 1] = v.y;
        sm[r][cg * 4 + 2] = v.z; sm[r][cg * 4 + 3] = v.w;
    }
    __syncthreads();
    {
        int v = t >> 3, kg = t & 7;
        __nv_bfloat16 h[4], l[4];
        #pragma unroll
        for (int j = 0; j < 4; j++) {
            float f = sm[kg * 4 + j][v];
            h[j] = __float2bfloat16(f);
            l[j] = __float2bfloat16(f - __bfloat162float(h[j]));
        }
        size_t off = (size_t)(b * V_DIM + v0 + v) * SEQ_K + k0 + kg * 4;
        *(uint2*)(gth + off) = *(const uint2*)h;
        *(uint2*)(gtl + off) = *(const uint2*)l;
    }
}

// ================= flash attention on mma.sync (split-bf16) =================
// 128q CTA, 512 threads (16 warps, 4m x 4n), 16 key-tiles of 64.
// phi double-buffered (prefetch kt+1 during kt); hi-fragments deduplicated
// by k0-outer / split-term-inner loop order.
#define OFF_TH  0u                 // theta hi [128][72]
#define OFF_TL  9216u              // theta lo
#define OFF_FB(buf) (18432u + (buf) * 9216u)   // phi buf: hi [64][72] then lo
#define OFF_GH  36864u             // gT hi [256][72]
#define OFF_GL  55296u
#define OFF_SPH 73728u             // P hi [128][72]
#define OFF_SPL 82944u
#define ATTN_BF16_ELEMS 92160u
#define ATTN_SMEM_BYTES (92160 * 2 + 2 * 512 * 4)   // 188416

__global__ __launch_bounds__(512, 1) void attn_k(
    const float* __restrict__ proj,
    const __nv_bfloat16* __restrict__ fhi, const __nv_bfloat16* __restrict__ flo,
    const __nv_bfloat16* __restrict__ gth, const __nv_bfloat16* __restrict__ gtl,
    __nv_bfloat16* __restrict__ thi, __nv_bfloat16* __restrict__ tlo)
{
    extern __shared__ __nv_bfloat16 sb[];
    float* redA = (float*)(sb + ATTN_BF16_ELEMS);
    float* redB = redA + 512;

    const uint32_t sb32 = smem_u32(sb);
    const int tid  = threadIdx.x;
    const int lane = tid & 31;
    const int wid  = tid >> 5;
    const int warpM = wid >> 2;
    const int warpN = wid & 3;
    const int b  = blockIdx.y;
    const int qt = blockIdx.x;
    const int qbase = b * SEQ_Q + qt * 128;
    const float L2E = 1.4426950408889634f;

    // issue phi(0) into buf 0
    auto issue_phi = [&](int kt, int buf) {
        const size_t fb = (size_t)(b * SEQ_K + kt * 64) * 64;
        const uint32_t fB = OFF_FB(buf);
        #pragma unroll
        for (int i = 0; i < 2; i++) {
            int id = tid + i * 512;
            int half = id >> 9, j = id & 511;
            int row = j >> 3, c = j & 7;
            CP_ASYNC16(sb32 + (fB + half * 4608u + row * 72 + c * 8) * 2,
                       (half ? flo : fhi) + fb + (size_t)row * 64 + c * 8);
        }
        CP_COMMIT();
    };
    issue_phi(0, 0);

    // theta (scaled by log2e) -> smem hi/lo
    #pragma unroll
    for (int i = tid; i < 128 * 16; i += 512) {
        int q = i >> 4, c4 = i & 15;
        float4 v = *(const float4*)(proj + (size_t)(qbase + q) * NPROJ + c4 * 4);
        float f[4] = {v.x * L2E, v.y * L2E, v.z * L2E, v.w * L2E};
        __nv_bfloat16 h[4], l[4];
        #pragma unroll
        for (int j = 0; j < 4; j++) {
            h[j] = __float2bfloat16(f[j]);
            l[j] = __float2bfloat16(f[j] - __bfloat162float(h[j]));
        }
        uint32_t o = q * 72 + c4 * 4;
        *(uint2*)(sb + OFF_TH + o) = *(const uint2*)h;
        *(uint2*)(sb + OFF_TL + o) = *(const uint2*)l;
    }

    float acc[2][8][4];
    float m[2][2], l[2][2];
    #pragma unroll
    for (int mf = 0; mf < 2; mf++) {
        m[mf][0] = -1e30f; m[mf][1] = -1e30f;
        l[mf][0] = 0.f;    l[mf][1] = 0.f;
        #pragma unroll
        for (int nf = 0; nf < 8; nf++)
            #pragma unroll
            for (int c = 0; c < 4; c++) acc[mf][nf][c] = 0.f;
    }

    const int rowA = warpM * 32 + (lane & 15);
    const int rq   = lane >> 2;
    const int cq2  = (lane & 3) * 2;

    for (int kt = 0; kt < 16; kt++) {
        const int buf = kt & 1;
        __syncthreads();   // PV(kt-1) done: g buffer, P, red free
        // issue g(kt)
        {
            const size_t gb = (size_t)b * V_DIM * SEQ_K + kt * 64;
            #pragma unroll
            for (int i = 0; i < 8; i++) {
                int id = tid + i * 512;
                int half = id >> 11, j = id & 2047;
                int v = j >> 3, c = j & 7;
                CP_ASYNC16(sb32 + ((half ? OFF_GL : OFF_GH) + v * 72 + c * 8) * 2,
                           (half ? gtl : gth) + gb + (size_t)v * SEQ_K + c * 8);
            }
            CP_COMMIT();
        }
        CP_WAIT(1);        // phi(kt) complete (g(kt) may remain)
        __syncthreads();

        // ---- QK (k0 outer, split-terms inner; hi frags loaded once) ----
        const uint32_t fH = OFF_FB(buf), fL = fH + 4608u;
        float aq[2][2][4];
        #pragma unroll
        for (int mf = 0; mf < 2; mf++)
            #pragma unroll
            for (int nf = 0; nf < 2; nf++)
                #pragma unroll
                for (int c = 0; c < 4; c++) aq[mf][nf][c] = 0.f;

        #pragma unroll
        for (int k0 = 0; k0 < 64; k0 += 16) {
            uint32_t th0[4], th1[4], tl0[4], tl1[4], fh[4], fl[4];
            uint32_t colA = k0 + (lane >> 4) * 8;
            LDSM_X4(th0[0], th0[1], th0[2], th0[3], sb32 + (OFF_TH + (rowA) * 72 + colA) * 2);
            LDSM_X4(th1[0], th1[1], th1[2], th1[3], sb32 + (OFF_TH + (rowA + 16) * 72 + colA) * 2);
            LDSM_X4(tl0[0], tl0[1], tl0[2], tl0[3], sb32 + (OFF_TL + (rowA) * 72 + colA) * 2);
            LDSM_X4(tl1[0], tl1[1], tl1[2], tl1[3], sb32 + (OFF_TL + (rowA + 16) * 72 + colA) * 2);
            int g = lane >> 3, rr = lane & 7;
            uint32_t brow = (warpN * 16 + (g & 2) * 4 + rr) * 72 + k0 + (g & 1) * 8;
            LDSM_X4(fh[0], fh[1], fh[2], fh[3], sb32 + (fH + brow) * 2);
            LDSM_X4(fl[0], fl[1], fl[2], fl[3], sb32 + (fL + brow) * 2);
            MMA16816(aq[0][0], th0, fh[0], fh[1]);
            MMA16816(aq[0][1], th0, fh[2], fh[3]);
            MMA16816(aq[1][0], th1, fh[0], fh[1]);
            MMA16816(aq[1][1], th1, fh[2], fh[3]);
            MMA16816(aq[0][0], tl0, fh[0], fh[1]);
            MMA16816(aq[0][1], tl0, fh[2], fh[3]);
            MMA16816(aq[1][0], tl1, fh[0], fh[1]);
            MMA16816(aq[1][1], tl1, fh[2], fh[3]);
            MMA16816(aq[0][0], th0, fl[0], fl[1]);
            MMA16816(aq[0][1], th0, fl[2], fl[3]);
            MMA16816(aq[1][0], th1, fl[0], fl[1]);
            MMA16816(aq[1][1], th1, fl[2], fl[3]);
        }

        // prefetch phi(kt+1) into other buffer (no sync needed: 2-buf + per-kt barriers)
        if (kt + 1 < 16) issue_phi(kt + 1, buf ^ 1);

        // ---- online softmax ----
        float mx[2][2];
        #pragma unroll
        for (int mf = 0; mf < 2; mf++)
            #pragma unroll
            for (int h = 0; h < 2; h++) {
                float t = fmaxf(fmaxf(aq[mf][0][h * 2], aq[mf][0][h * 2 + 1]),
                                fmaxf(aq[mf][1][h * 2], aq[mf][1][h * 2 + 1]));
                t = fmaxf(t, __shfl_xor_sync(0xffffffffu, t, 1));
                t = fmaxf(t, __shfl_xor_sync(0xffffffffu, t, 2));
                mx[mf][h] = t;
            }
        if ((lane & 3) == 0) {
            #pragma unroll
            for (int mf = 0; mf < 2; mf++)
                #pragma unroll
                for (int h = 0; h < 2; h++)
                    redA[warpN * 128 + warpM * 32 + mf * 16 + h * 8 + rq] = mx[mf][h];
        }
        __syncthreads();

        float mnew[2][2], scale[2][2], rsum[2][2];
        #pragma unroll
        for (int mf = 0; mf < 2; mf++)
            #pragma unroll
            for (int h = 0; h < 2; h++) {
                int r = warpM * 32 + mf * 16 + h * 8 + rq;
                float v = m[mf][h];
                #pragma unroll
                for (int w = 0; w < 4; w++) v = fmaxf(v, redA[w * 128 + r]);
                mnew[mf][h] = v;
                rsum[mf][h] = 0.f;
            }

        #pragma unroll
        for (int mf = 0; mf < 2; mf++)
            #pragma unroll
            for (int nf = 0; nf < 2; nf++)
                #pragma unroll
                for (int h = 0; h < 2; h++) {
                    float p0 = ex2f(aq[mf][nf][h * 2]     - mnew[mf][h]);
                    float p1 = ex2f(aq[mf][nf][h * 2 + 1] - mnew[mf][h]);
                    rsum[mf][h] += p0 + p1;
                    __nv_bfloat16 h0 = __float2bfloat16(p0);
                    __nv_bfloat16 h1 = __float2bfloat16(p1);
                    __nv_bfloat16 l0 = __float2bfloat16(p0 - __bfloat162float(h0));
                    __nv_bfloat16 l1 = __float2bfloat16(p1 - __bfloat162float(h1));
                    int row = warpM * 32 + mf * 16 + h * 8 + rq;
                    int col = warpN * 16 + nf * 8 + cq2;
                    __nv_bfloat162 hv; hv.x = h0; hv.y = h1;
                    __nv_bfloat162 lv; lv.x = l0; lv.y = l1;
                    *(__nv_bfloat162*)(sb + OFF_SPH + row * 72 + col) = hv;
                    *(__nv_bfloat162*)(sb + OFF_SPL + row * 72 + col) = lv;
                }
        #pragma unroll
        for (int mf = 0; mf < 2; mf++)
            #pragma unroll
            for (int h = 0; h < 2; h++) {
                float t = rsum[mf][h];
                t += __shfl_xor_sync(0xffffffffu, t, 1);
                t += __shfl_xor_sync(0xffffffffu, t, 2);
                rsum[mf][h] = t;
                scale[mf][h] = ex2f(m[mf][h] - mnew[mf][h]);
                m[mf][h] = mnew[mf][h];
            }
        if ((lane & 3) == 0) {
            #pragma unroll
            for (int mf = 0; mf < 2; mf++)
                #pragma unroll
                for (int h = 0; h < 2; h++)
                    redB[warpN * 128 + warpM * 32 + mf * 16 + h * 8 + rq] = rsum[mf][h];
        }
        if (kt + 1 < 16) { CP_WAIT(1); }   // g(kt) done (phi(kt+1) pending)
        else             { CP_WAIT(0); }
        __syncthreads();   // g + P + redB visible to all

        #pragma unroll
        for (int mf = 0; mf < 2; mf++)
            #pragma unroll
            for (int h = 0; h < 2; h++) {
                int r = warpM * 32 + mf * 16 + h * 8 + rq;
                float s = 0.f;
                #pragma unroll
                for (int w = 0; w < 4; w++) s += redB[w * 128 + r];
                l[mf][h] = l[mf][h] * scale[mf][h] + s;
            }
        #pragma unroll
        for (int mf = 0; mf < 2; mf++)
            #pragma unroll
            for (int nf = 0; nf < 8; nf++) {
                acc[mf][nf][0] *= scale[mf][0];
                acc[mf][nf][1] *= scale[mf][0];
                acc[mf][nf][2] *= scale[mf][1];
                acc[mf][nf][3] *= scale[mf][1];
            }

        // ---- PV (k0/j2 outer, split-terms inner; hi frags loaded once) ----
        #pragma unroll
        for (int k0 = 0; k0 < 64; k0 += 16) {
            uint32_t ph0[4], ph1[4], pl0[4], pl1[4];
            uint32_t colA = k0 + (lane >> 4) * 8;
            LDSM_X4(ph0[0], ph0[1], ph0[2], ph0[3], sb32 + (OFF_SPH + (rowA) * 72 + colA) * 2);
            LDSM_X4(ph1[0], ph1[1], ph1[2], ph1[3], sb32 + (OFF_SPH + (rowA + 16) * 72 + colA) * 2);
            LDSM_X4(pl0[0], pl0[1], pl0[2], pl0[3], sb32 + (OFF_SPL + (rowA) * 72 + colA) * 2);
            LDSM_X4(pl1[0], pl1[1], pl1[2], pl1[3], sb32 + (OFF_SPL + (rowA + 16) * 72 + colA) * 2);
            int g = lane >> 3, rr = lane & 7;
            #pragma unroll
            for (int j2 = 0; j2 < 4; j2++) {
                uint32_t gh[4], gl[4];
                uint32_t brow = (warpN * 64 + j2 * 16 + (g & 2) * 4 + rr) * 72 + k0 + (g & 1) * 8;
                LDSM_X4(gh[0], gh[1], gh[2], gh[3], sb32 + (OFF_GH + brow) * 2);
                LDSM_X4(gl[0], gl[1], gl[2], gl[3], sb32 + (OFF_GL + brow) * 2);
                MMA16816(acc[0][j2 * 2 + 0], ph0, gh[0], gh[1]);
                MMA16816(acc[0][j2 * 2 + 1], ph0, gh[2], gh[3]);
                MMA16816(acc[1][j2 * 2 + 0], ph1, gh[0], gh[1]);
                MMA16816(acc[1][j2 * 2 + 1], ph1, gh[2], gh[3]);
                MMA16816(acc[0][j2 * 2 + 0], pl0, gh[0], gh[1]);
                MMA16816(acc[0][j2 * 2 + 1], pl0, gh[2], gh[3]);
                MMA16816(acc[1][j2 * 2 + 0], pl1, gh[0], gh[1]);
                MMA16816(acc[1][j2 * 2 + 1], pl1, gh[2], gh[3]);
                MMA16816(acc[0][j2 * 2 + 0], ph0, gl[0], gl[1]);
                MMA16816(acc[0][j2 * 2 + 1], ph0, gl[2], gl[3]);
                MMA16816(acc[1][j2 * 2 + 0], ph1, gl[0], gl[1]);
                MMA16816(acc[1][j2 * 2 + 1], ph1, gl[2], gl[3]);
            }
        }
    }

    // ---- epilogue: tmp = acc / l -> bf16 hi/lo ----
    #pragma unroll
    for (int mf = 0; mf < 2; mf++)
        #pragma unroll
        for (int h = 0; h < 2; h++) {
            float inv = 1.f / l[mf][h];
            int row = qbase + warpM * 32 + mf * 16 + h * 8 + rq;
            #pragma unroll
            for (int nf = 0; nf < 8; nf++) {
                int col = warpN * 64 + nf * 8 + cq2;
                float v0 = acc[mf][nf][h * 2]     * inv;
                float v1 = acc[mf][nf][h * 2 + 1] * inv;
                __nv_bfloat16 h0 = __float2bfloat16(v0);
                __nv_bfloat16 h1 = __float2bfloat16(v1);
                __nv_bfloat16 l0 = __float2bfloat16(v0 - __bfloat162float(h0));
                __nv_bfloat16 l1 = __float2bfloat16(v1 - __bfloat162float(h1));
                __nv_bfloat162 hv; hv.x = h0; hv.y = h1;
                __nv_bfloat162 lv; lv.x = l0; lv.y = l1;
                *(__nv_bfloat162*)(thi + (size_t)row * V_DIM + col) = hv;
                *(__nv_bfloat162*)(tlo + (size_t)row * V_DIM + col) = lv;
            }
        }
}

// ---------------- launch ----------------
extern "C" void kernel_launch(void* const* d_in, const int* in_sizes, int n_in,
                              void* d_out, int out_size)
{
    const float* x     = (const float*)d_in[0];
    const float* Wt    = (const float*)d_in[1];
    const float* Wp    = (const float*)d_in[2];
    const float* Wg    = (const float*)d_in[3];
    const float* Wo    = (const float*)d_in[4];
    const float* gamma = (const float*)d_in[5];
    float* out = (float*)d_out;

    float *proj, *gP;
    __nv_bfloat16 *xhi, *xlo, *thi, *tlo, *Bph, *Bpl, *Boh, *Bol, *fhi, *flo, *gth, *gtl;
    cudaGetSymbolAddress((void**)&proj, g_proj);
    cudaGetSymbolAddress((void**)&gP,   g_gP);
    cudaGetSymbolAddress((void**)&xhi,  g_xhi);
    cudaGetSymbolAddress((void**)&xlo,  g_xlo);
    cudaGetSymbolAddress((void**)&thi,  g_thi);
    cudaGetSymbolAddress((void**)&tlo,  g_tlo);
    cudaGetSymbolAddress((void**)&Bph,  g_Bp_hi);
    cudaGetSymbolAddress((void**)&Bpl,  g_Bp_lo);
    cudaGetSymbolAddress((void**)&Boh,  g_Bo_hi);
    cudaGetSymbolAddress((void**)&Bol,  g_Bo_lo);
    cudaGetSymbolAddress((void**)&fhi,  g_fhi);
    cudaGetSymbolAddress((void**)&flo,  g_flo);
    cudaGetSymbolAddress((void**)&gth,  g_gth);
    cudaGetSymbolAddress((void**)&gtl,  g_gtl);

    cudaFuncSetAttribute(gemm_mma<512>, cudaFuncAttributeMaxDynamicSharedMemorySize, GEMM_SMEM_BYTES);
    cudaFuncSetAttribute(gemm_mma<256>, cudaFuncAttributeMaxDynamicSharedMemorySize, GEMM_SMEM_BYTES);
    cudaFuncSetAttribute(attn_k, cudaFuncAttributeMaxDynamicSharedMemorySize, ATTN_SMEM_BYTES);

    convert_x_k<<<(M_ROWS * C_IN / 8 + 255) / 256, 256>>>(x, xhi, xlo);
    pack_proj_k<<<(NPROJ * C_IN + 255) / 256, 256>>>(Wt, Wp, Wg, Bph, Bpl);
    pack_wo_k<<<(C_IN * V_DIM + 255) / 256, 256>>>(Wo, Boh, Bol);
    gemm_mma<512><<<dim3(NPROJ / 128, M_ROWS / 256), 256, GEMM_SMEM_BYTES>>>(
        xhi, xlo, Bph, Bpl, proj, NPROJ, nullptr, nullptr);
    {
        int total = BATCH * SEQ_K * (D_DIM / 4) + BATCH * SEQ_K * (V_DIM / 4);
        pool_k<<<(total + 255) / 256, 256>>>(proj, fhi, flo, gP);
    }
    transT_g_k<<<dim3(V_DIM / 32, SEQ_K / 32, BATCH), 256>>>(gP, gth, gtl);
    attn_k<<<dim3(SEQ_Q / 128, BATCH), 512, ATTN_SMEM_BYTES>>>(
        proj, fhi, flo, gth, gtl, thi, tlo);
    gemm_mma<256><<<dim3(C_IN / 128, M_ROWS / 256), 256, GEMM_SMEM_BYTES>>>(
        thi, tlo, Boh, Bol, out, C_IN, x, gamma);
}

// round 9
// speedup vs baseline: 6.2911x; 1.0341x over previous
#include <cuda_runtime.h>
#include <cuda_bf16.h>
#include <cuda_fp16.h>
#include <math.h>
#include <cstdint>

// x: [16, 64, 64, 512] -> rows M = 65536, C = 512
#define M_ROWS 65536
#define C_IN   512
#define D_DIM  64
#define V_DIM  256
#define BATCH  16
#define SEQ_Q  4096
#define SEQ_K  1024
#define NPROJ  384   // 64 theta | 64 phi | 256 g

// ---------------- scratch (device globals; no allocation allowed) ----------------
__device__ float          g_proj [M_ROWS * NPROJ];
__device__ float          g_gP   [BATCH * SEQ_K * V_DIM];
__device__ __half         g_xhi  [M_ROWS * C_IN];
__device__ __half         g_xlo  [M_ROWS * C_IN];
__device__ __half         g_thi  [M_ROWS * V_DIM];
__device__ __half         g_tlo  [M_ROWS * V_DIM];
__device__ __half         g_Bp_hi[NPROJ * C_IN];
__device__ __half         g_Bp_lo[NPROJ * C_IN];
__device__ __half         g_Bo_hi[C_IN * V_DIM];
__device__ __half         g_Bo_lo[C_IN * V_DIM];
__device__ __nv_bfloat16  g_fhi  [BATCH * SEQ_K * D_DIM];
__device__ __nv_bfloat16  g_flo  [BATCH * SEQ_K * D_DIM];
__device__ __nv_bfloat16  g_gth  [BATCH * V_DIM * SEQ_K];
__device__ __nv_bfloat16  g_gtl  [BATCH * V_DIM * SEQ_K];

// ================= baseline-ISA helpers =================
__device__ __forceinline__ uint32_t smem_u32(const void* p) {
    uint32_t a;
    asm("{ .reg .u64 t; cvta.to.shared.u64 t, %1; cvt.u32.u64 %0, t; }" : "=r"(a) : "l"(p));
    return a;
}
__device__ __forceinline__ float ex2f(float x) {
    float y; asm("ex2.approx.f32 %0, %1;" : "=f"(y) : "f"(x)); return y;
}
#define CP_ASYNC16(dst, src) \
    asm volatile("cp.async.cg.shared.global [%0], [%1], 16;" :: "r"(dst), "l"(src))
#define CP_COMMIT() asm volatile("cp.async.commit_group;" ::: "memory")
#define CP_WAIT(N)  asm volatile("cp.async.wait_group %0;" :: "n"(N) : "memory")
#define LDSM_X4(r0, r1, r2, r3, addr) \
    asm volatile("ldmatrix.sync.aligned.m8n8.x4.shared.b16 {%0,%1,%2,%3}, [%4];" \
                 : "=r"(r0), "=r"(r1), "=r"(r2), "=r"(r3) : "r"(addr))
// bf16 in, fp32 acc
#define MMA16816(d, a, b0v, b1v) \
    asm volatile("mma.sync.aligned.m16n8k16.row.col.f32.bf16.bf16.f32 " \
                 "{%0,%1,%2,%3}, {%4,%5,%6,%7}, {%8,%9}, {%0,%1,%2,%3};" \
                 : "+f"((d)[0]), "+f"((d)[1]), "+f"((d)[2]), "+f"((d)[3]) \
                 : "r"((a)[0]), "r"((a)[1]), "r"((a)[2]), "r"((a)[3]), \
                   "r"(b0v), "r"(b1v))
// fp16 in, fp32 acc (full-precision main term)
#define MMA16816F(d, a, b0v, b1v) \
    asm volatile("mma.sync.aligned.m16n8k16.row.col.f32.f16.f16.f32 " \
                 "{%0,%1,%2,%3}, {%4,%5,%6,%7}, {%8,%9}, {%0,%1,%2,%3};" \
                 : "+f"((d)[0]), "+f"((d)[1]), "+f"((d)[2]), "+f"((d)[3]) \
                 : "r"((a)[0]), "r"((a)[1]), "r"((a)[2]), "r"((a)[3]), \
                   "r"(b0v), "r"(b1v))
// fp16 in, fp16 acc (2x rate; correction terms only)
#define MMA16816H(d, a, b0v, b1v) \
    asm volatile("mma.sync.aligned.m16n8k16.row.col.f16.f16.f16.f16 " \
                 "{%0,%1}, {%2,%3,%4,%5}, {%6,%7}, {%0,%1};" \
                 : "+r"((d)[0]), "+r"((d)[1]) \
                 : "r"((a)[0]), "r"((a)[1]), "r"((a)[2]), "r"((a)[3]), \
                   "r"(b0v), "r"(b1v))

// ================= conversion / packing (fp16 hi/lo) =================
__global__ void convert_x_k(const float* __restrict__ x,
                            __half* __restrict__ xhi, __half* __restrict__ xlo)
{
    size_t i = ((size_t)blockIdx.x * blockDim.x + threadIdx.x) * 8;
    if (i >= (size_t)M_ROWS * C_IN) return;
    float4 a = *(const float4*)(x + i);
    float4 b = *(const float4*)(x + i + 4);
    float v[8] = {a.x, a.y, a.z, a.w, b.x, b.y, b.z, b.w};
    __half h[8], l[8];
    #pragma unroll
    for (int j = 0; j < 8; j++) {
        h[j] = __float2half(v[j]);
        l[j] = __float2half(v[j] - __half2float(h[j]));
    }
    *(uint4*)(xhi + i) = *(const uint4*)h;
    *(uint4*)(xlo + i) = *(const uint4*)l;
}

__global__ void pack_proj_k(const float* __restrict__ Wt, const float* __restrict__ Wp,
                            const float* __restrict__ Wg,
                            __half* __restrict__ bhi, __half* __restrict__ blo)
{
    int i = blockIdx.x * blockDim.x + threadIdx.x;
    if (i >= NPROJ * C_IN) return;
    int n = i / C_IN, k = i % C_IN;
    float v;
    if (n < 64)       v = Wt[k * 64 + n];
    else if (n < 128) v = Wp[k * 64 + (n - 64)];
    else              v = Wg[k * 256 + (n - 128)];
    __half h = __float2half(v);
    bhi[i] = h;
    blo[i] = __float2half(v - __half2float(h));
}

__global__ void pack_wo_k(const float* __restrict__ Wo,
                          __half* __restrict__ bhi, __half* __restrict__ blo)
{
    int i = blockIdx.x * blockDim.x + threadIdx.x;
    if (i >= C_IN * V_DIM) return;
    int n = i / V_DIM, k = i % V_DIM;
    float v = Wo[k * C_IN + n];
    __half h = __float2half(v);
    bhi[i] = h;
    blo[i] = __float2half(v - __half2float(h));
}

// ================= fp16 mixed-acc GEMM: 128x128x32, 3-stage, warp 64x32 =================
// C = (Ah+Al)(Bh+Bl)^T ~= AhBh [f32 acc] + AlBh [f16 acc] + AhBl [f16 acc].
// Per chunk both hi and lo of A and B are resident; corrections kept in fp16
// registers across the whole K loop, folded in at the epilogue.
#define BK      32
#define ASTRIDE 40
#define STAGES  3
#define G_AR    (128 * ASTRIDE * 2)              // bytes per array per stage
#define G_STAGE (4 * G_AR)                       // Ah, Al, Bh, Bl
#define GEMM_SMEM_BYTES (STAGES * G_STAGE)       // 122880

template <int KB>
__global__ __launch_bounds__(256, 1) void gemm_mma(
    const __half* __restrict__ Ahi, const __half* __restrict__ Alo,
    const __half* __restrict__ Bhi, const __half* __restrict__ Blo,
    float* __restrict__ C, int ldc,
    const float* __restrict__ res, const float* __restrict__ gammaP)
{
    extern __shared__ __half sg[];
    const uint32_t sbase = smem_u32(sg);

    const int tid  = threadIdx.x;
    const int lane = tid & 31;
    const int wid  = tid >> 5;
    const int warpM = wid >> 2;     // 0..1 -> 64 rows each
    const int warpN = wid & 3;      // 0..3 -> 32 cols each
    const int m0 = blockIdx.y * 128;
    const int n0 = blockIdx.x * 128;

    constexpr int CHUNKS = KB / BK;

    auto load_chunk = [&](int c, int stg) {
        const int kcol = c * BK;
        const uint32_t base = sbase + stg * G_STAGE;
        #pragma unroll
        for (int it = 0; it < 8; it++) {
            int idx = tid + it * 256;              // 0..2047
            int arr = idx >> 9;                    // 0:Ah 1:Al 2:Bh 3:Bl
            int j = idx & 511;
            int row = j >> 2, c16 = j & 3;
            const __half* src =
                (arr == 0) ? Ahi + (size_t)(m0 + row) * KB + kcol + c16 * 8 :
                (arr == 1) ? Alo + (size_t)(m0 + row) * KB + kcol + c16 * 8 :
                (arr == 2) ? Bhi + (size_t)(n0 + row) * KB + kcol + c16 * 8 :
                             Blo + (size_t)(n0 + row) * KB + kcol + c16 * 8;
            CP_ASYNC16(base + arr * G_AR + (row * ASTRIDE + c16 * 8) * 2, src);
        }
        CP_COMMIT();
    };

    float    accF[4][4][4];
    uint32_t accA[4][4][2];   // AlBh, fp16 pairs
    uint32_t accB[4][4][2];   // AhBl
    #pragma unroll
    for (int i = 0; i < 4; i++)
        #pragma unroll
        for (int j = 0; j < 4; j++) {
            #pragma unroll
            for (int r = 0; r < 4; r++) accF[i][j][r] = 0.f;
            accA[i][j][0] = accA[i][j][1] = 0u;
            accB[i][j][0] = accB[i][j][1] = 0u;
        }

    #pragma unroll
    for (int s = 0; s < STAGES - 1; s++) load_chunk(s, s);

    for (int c = 0; c < CHUNKS; c++) {
        CP_WAIT(STAGES - 2);
        __syncthreads();

        const uint32_t base = sbase + (c % STAGES) * G_STAGE;
        const uint32_t ahB = base, alB = base + G_AR, bhB = base + 2 * G_AR, blB = base + 3 * G_AR;
        #pragma unroll
        for (int k0 = 0; k0 < BK; k0 += 16) {
            uint32_t ah[4][4], al[4][4];
            uint32_t colA = k0 + (lane >> 4) * 8;
            #pragma unroll
            for (int i = 0; i < 4; i++) {
                uint32_t roff = ((warpM * 64 + i * 16 + (lane & 15)) * ASTRIDE + colA) * 2;
                LDSM_X4(ah[i][0], ah[i][1], ah[i][2], ah[i][3], ahB + roff);
                LDSM_X4(al[i][0], al[i][1], al[i][2], al[i][3], alB + roff);
            }
            uint32_t bh[2][4], bl[2][4];
            int g = lane >> 3, rr = lane & 7;
            #pragma unroll
            for (int j2 = 0; j2 < 2; j2++) {
                uint32_t roff = ((warpN * 32 + j2 * 16 + (g & 2) * 4 + rr) * ASTRIDE
                                 + k0 + (g & 1) * 8) * 2;
                LDSM_X4(bh[j2][0], bh[j2][1], bh[j2][2], bh[j2][3], bhB + roff);
                LDSM_X4(bl[j2][0], bl[j2][1], bl[j2][2], bl[j2][3], blB + roff);
            }
            #pragma unroll
            for (int i = 0; i < 4; i++)
                #pragma unroll
                for (int j = 0; j < 4; j++) {
                    uint32_t b0h = bh[j >> 1][(j & 1) * 2], b1h = bh[j >> 1][(j & 1) * 2 + 1];
                    uint32_t b0l = bl[j >> 1][(j & 1) * 2], b1l = bl[j >> 1][(j & 1) * 2 + 1];
                    MMA16816F(accF[i][j], ah[i], b0h, b1h);
                    MMA16816H(accA[i][j], al[i], b0h, b1h);
                    MMA16816H(accB[i][j], ah[i], b0l, b1l);
                }
        }
        if (c + STAGES - 1 < CHUNKS) load_chunk(c + STAGES - 1, (c + STAGES - 1) % STAGES);
        else CP_COMMIT();
    }

    // epilogue: total = accF + tofloat(accA) + tofloat(accB); optional gamma*acc + res
    const float gamma = res ? *gammaP : 0.f;
    #pragma unroll
    for (int i = 0; i < 4; i++) {
        #pragma unroll
        for (int j = 0; j < 4; j++) {
            float2 a01 = __half22float2(*(__half2*)&accA[i][j][0]);
            float2 a23 = __half22float2(*(__half2*)&accA[i][j][1]);
            float2 b01 = __half22float2(*(__half2*)&accB[i][j][0]);
            float2 b23 = __half22float2(*(__half2*)&accB[i][j][1]);
            float t0 = accF[i][j][0] + a01.x + b01.x;
            float t1 = accF[i][j][1] + a01.y + b01.y;
            float t2 = accF[i][j][2] + a23.x + b23.x;
            float t3 = accF[i][j][3] + a23.y + b23.y;
            int gr = m0 + warpM * 64 + i * 16 + (lane >> 2);
            int gc = n0 + warpN * 32 + j * 8 + (lane & 3) * 2;
            size_t off0 = (size_t)gr * ldc + gc;
            size_t off1 = off0 + (size_t)8 * ldc;
            if (res) {
                float2 r0 = *(const float2*)(res + off0);
                float2 r1 = *(const float2*)(res + off1);
                *(float2*)(C + off0) = make_float2(fmaf(gamma, t0, r0.x), fmaf(gamma, t1, r0.y));
                *(float2*)(C + off1) = make_float2(fmaf(gamma, t2, r1.x), fmaf(gamma, t3, r1.y));
            } else {
                *(float2*)(C + off0) = make_float2(t0, t1);
                *(float2*)(C + off1) = make_float2(t2, t3);
            }
        }
    }
}

// ---------------- 2x2 maxpool: phi -> bf16 hi/lo directly; g -> fp32 ----------------
__global__ void pool_k(const float* __restrict__ proj,
                       __nv_bfloat16* __restrict__ fhi, __nv_bfloat16* __restrict__ flo,
                       float* __restrict__ gP)
{
    const int NPHI4 = BATCH * SEQ_K * (D_DIM / 4);
    const int NG4   = BATCH * SEQ_K * (V_DIM / 4);
    int i = blockIdx.x * blockDim.x + threadIdx.x;
    if (i < NPHI4) {
        int bp = i >> 4, c4 = i & 15;
        int b = bp >> 10, ij = bp & 1023, ii = ij >> 5, jj = ij & 31;
        int r = b * 4096 + ii * 128 + jj * 2;
        const float* base = proj + 64 + (size_t)c4 * 4;
        float4 v0 = *(const float4*)(base + (size_t)r * NPROJ);
        float4 v1 = *(const float4*)(base + (size_t)(r + 1) * NPROJ);
        float4 v2 = *(const float4*)(base + (size_t)(r + 64) * NPROJ);
        float4 v3 = *(const float4*)(base + (size_t)(r + 65) * NPROJ);
        float f[4];
        f[0] = fmaxf(fmaxf(v0.x, v1.x), fmaxf(v2.x, v3.x));
        f[1] = fmaxf(fmaxf(v0.y, v1.y), fmaxf(v2.y, v3.y));
        f[2] = fmaxf(fmaxf(v0.z, v1.z), fmaxf(v2.z, v3.z));
        f[3] = fmaxf(fmaxf(v0.w, v1.w), fmaxf(v2.w, v3.w));
        __nv_bfloat16 h[4], l[4];
        #pragma unroll
        for (int j = 0; j < 4; j++) {
            h[j] = __float2bfloat16(f[j]);
            l[j] = __float2bfloat16(f[j] - __bfloat162float(h[j]));
        }
        size_t off = (size_t)bp * 64 + c4 * 4;
        *(uint2*)(fhi + off) = *(const uint2*)h;
        *(uint2*)(flo + off) = *(const uint2*)l;
    } else {
        int j = i - NPHI4;
        if (j < NG4) {
            int bp = j >> 6, c4 = j & 63;
            int b = bp >> 10, ij = bp & 1023, ii = ij >> 5, jj = ij & 31;
            int r = b * 4096 + ii * 128 + jj * 2;
            const float* base = proj + 128 + (size_t)c4 * 4;
            float4 v0 = *(const float4*)(base + (size_t)r * NPROJ);
            float4 v1 = *(const float4*)(base + (size_t)(r + 1) * NPROJ);
            float4 v2 = *(const float4*)(base + (size_t)(r + 64) * NPROJ);
            float4 v3 = *(const float4*)(base + (size_t)(r + 65) * NPROJ);
            float4 o;
            o.x = fmaxf(fmaxf(v0.x, v1.x), fmaxf(v2.x, v3.x));
            o.y = fmaxf(fmaxf(v0.y, v1.y), fmaxf(v2.y, v3.y));
            o.z = fmaxf(fmaxf(v0.z, v1.z), fmaxf(v2.z, v3.z));
            o.w = fmaxf(fmaxf(v0.w, v1.w), fmaxf(v2.w, v3.w));
            *((float4*)(gP + (size_t)bp * 256) + c4) = o;
        }
    }
}

// ---------------- transpose+split g (bf16, unchanged) ----------------
__global__ void transT_g_k(const float* __restrict__ gP,
                           __nv_bfloat16* __restrict__ gth, __nv_bfloat16* __restrict__ gtl)
{
    __shared__ float sm[32][33];
    const int t = threadIdx.x;
    const int v0 = blockIdx.x * 32;
    const int k0 = blockIdx.y * 32;
    const int b  = blockIdx.z;
    {
        int r = t >> 3, cg = t & 7;
        float4 v = *(const float4*)(gP + (size_t)(b * SEQ_K + k0 + r) * V_DIM + v0 + cg * 4);
        sm[r][cg * 4 + 0] = v.x; sm[r][cg * 4 + 1] = v.y;
        sm[r][cg * 4 + 2] = v.z; sm[r][cg * 4 + 3] = v.w;
    }
    __syncthreads();
    {
        int v = t >> 3, kg = t & 7;
        __nv_bfloat16 h[4], l[4];
        #pragma unroll
        for (int j = 0; j < 4; j++) {
            float f = sm[kg * 4 + j][v];
            h[j] = __float2bfloat16(f);
            l[j] = __float2bfloat16(f - __bfloat162float(h[j]));
        }
        size_t off = (size_t)(b * V_DIM + v0 + v) * SEQ_K + k0 + kg * 4;
        *(uint2*)(gth + off) = *(const uint2*)h;
        *(uint2*)(gtl + off) = *(const uint2*)l;
    }
}

// ================= flash attention on mma.sync (bf16 split; fp16 tmp out) =================
#define OFF_TH  0u
#define OFF_TL  9216u
#define OFF_FB(buf) (18432u + (buf) * 9216u)
#define OFF_GH  36864u
#define OFF_GL  55296u
#define OFF_SPH 73728u
#define OFF_SPL 82944u
#define ATTN_BF16_ELEMS 92160u
#define ATTN_SMEM_BYTES (92160 * 2 + 2 * 512 * 4)

__global__ __launch_bounds__(512, 1) void attn_k(
    const float* __restrict__ proj,
    const __nv_bfloat16* __restrict__ fhi, const __nv_bfloat16* __restrict__ flo,
    const __nv_bfloat16* __restrict__ gth, const __nv_bfloat16* __restrict__ gtl,
    __half* __restrict__ thi, __half* __restrict__ tlo)
{
    extern __shared__ __nv_bfloat16 sb[];
    float* redA = (float*)(sb + ATTN_BF16_ELEMS);
    float* redB = redA + 512;

    const uint32_t sb32 = smem_u32(sb);
    const int tid  = threadIdx.x;
    const int lane = tid & 31;
    const int wid  = tid >> 5;
    const int warpM = wid >> 2;
    const int warpN = wid & 3;
    const int b  = blockIdx.y;
    const int qt = blockIdx.x;
    const int qbase = b * SEQ_Q + qt * 128;
    const float L2E = 1.4426950408889634f;

    auto issue_phi = [&](int kt, int buf) {
        const size_t fb = (size_t)(b * SEQ_K + kt * 64) * 64;
        const uint32_t fB = OFF_FB(buf);
        #pragma unroll
        for (int i = 0; i < 2; i++) {
            int id = tid + i * 512;
            int half_ = id >> 9, j = id & 511;
            int row = j >> 3, c = j & 7;
            CP_ASYNC16(sb32 + (fB + half_ * 4608u + row * 72 + c * 8) * 2,
                       (half_ ? flo : fhi) + fb + (size_t)row * 64 + c * 8);
        }
        CP_COMMIT();
    };
    issue_phi(0, 0);

    #pragma unroll
    for (int i = tid; i < 128 * 16; i += 512) {
        int q = i >> 4, c4 = i & 15;
        float4 v = *(const float4*)(proj + (size_t)(qbase + q) * NPROJ + c4 * 4);
        float f[4] = {v.x * L2E, v.y * L2E, v.z * L2E, v.w * L2E};
        __nv_bfloat16 h[4], l[4];
        #pragma unroll
        for (int j = 0; j < 4; j++) {
            h[j] = __float2bfloat16(f[j]);
            l[j] = __float2bfloat16(f[j] - __bfloat162float(h[j]));
        }
        uint32_t o = q * 72 + c4 * 4;
        *(uint2*)(sb + OFF_TH + o) = *(const uint2*)h;
        *(uint2*)(sb + OFF_TL + o) = *(const uint2*)l;
    }

    float acc[2][8][4];
    float m[2][2], l[2][2];
    #pragma unroll
    for (int mf = 0; mf < 2; mf++) {
        m[mf][0] = -1e30f; m[mf][1] = -1e30f;
        l[mf][0] = 0.f;    l[mf][1] = 0.f;
        #pragma unroll
        for (int nf = 0; nf < 8; nf++)
            #pragma unroll
            for (int c = 0; c < 4; c++) acc[mf][nf][c] = 0.f;
    }

    const int rowA = warpM * 32 + (lane & 15);
    const int rq   = lane >> 2;
    const int cq2  = (lane & 3) * 2;

    for (int kt = 0; kt < 16; kt++) {
        const int buf = kt & 1;
        __syncthreads();
        {
            const size_t gb = (size_t)b * V_DIM * SEQ_K + kt * 64;
            #pragma unroll
            for (int i = 0; i < 8; i++) {
                int id = tid + i * 512;
                int half_ = id >> 11, j = id & 2047;
                int v = j >> 3, c = j & 7;
                CP_ASYNC16(sb32 + ((half_ ? OFF_GL : OFF_GH) + v * 72 + c * 8) * 2,
                           (half_ ? gtl : gth) + gb + (size_t)v * SEQ_K + c * 8);
            }
            CP_COMMIT();
        }
        CP_WAIT(1);
        __syncthreads();

        const uint32_t fH = OFF_FB(buf), fL = fH + 4608u;
        float aq[2][2][4];
        #pragma unroll
        for (int mf = 0; mf < 2; mf++)
            #pragma unroll
            for (int nf = 0; nf < 2; nf++)
                #pragma unroll
                for (int c = 0; c < 4; c++) aq[mf][nf][c] = 0.f;

        #pragma unroll
        for (int k0 = 0; k0 < 64; k0 += 16) {
            uint32_t th0[4], th1[4], tl0[4], tl1[4], fh[4], fl[4];
            uint32_t colA = k0 + (lane >> 4) * 8;
            LDSM_X4(th0[0], th0[1], th0[2], th0[3], sb32 + (OFF_TH + (rowA) * 72 + colA) * 2);
            LDSM_X4(th1[0], th1[1], th1[2], th1[3], sb32 + (OFF_TH + (rowA + 16) * 72 + colA) * 2);
            LDSM_X4(tl0[0], tl0[1], tl0[2], tl0[3], sb32 + (OFF_TL + (rowA) * 72 + colA) * 2);
            LDSM_X4(tl1[0], tl1[1], tl1[2], tl1[3], sb32 + (OFF_TL + (rowA + 16) * 72 + colA) * 2);
            int g = lane >> 3, rr = lane & 7;
            uint32_t brow = (warpN * 16 + (g & 2) * 4 + rr) * 72 + k0 + (g & 1) * 8;
            LDSM_X4(fh[0], fh[1], fh[2], fh[3], sb32 + (fH + brow) * 2);
            LDSM_X4(fl[0], fl[1], fl[2], fl[3], sb32 + (fL + brow) * 2);
            MMA16816(aq[0][0], th0, fh[0], fh[1]);
            MMA16816(aq[0][1], th0, fh[2], fh[3]);
            MMA16816(aq[1][0], th1, fh[0], fh[1]);
            MMA16816(aq[1][1], th1, fh[2], fh[3]);
            MMA16816(aq[0][0], tl0, fh[0], fh[1]);
            MMA16816(aq[0][1], tl0, fh[2], fh[3]);
            MMA16816(aq[1][0], tl1, fh[0], fh[1]);
            MMA16816(aq[1][1], tl1, fh[2], fh[3]);
            MMA16816(aq[0][0], th0, fl[0], fl[1]);
            MMA16816(aq[0][1], th0, fl[2], fl[3]);
            MMA16816(aq[1][0], th1, fl[0], fl[1]);
            MMA16816(aq[1][1], th1, fl[2], fl[3]);
        }

        if (kt + 1 < 16) issue_phi(kt + 1, buf ^ 1);

        float mx[2][2];
        #pragma unroll
        for (int mf = 0; mf < 2; mf++)
            #pragma unroll
            for (int h = 0; h < 2; h++) {
                float t = fmaxf(fmaxf(aq[mf][0][h * 2], aq[mf][0][h * 2 + 1]),
                                fmaxf(aq[mf][1][h * 2], aq[mf][1][h * 2 + 1]));
                t = fmaxf(t, __shfl_xor_sync(0xffffffffu, t, 1));
                t = fmaxf(t, __shfl_xor_sync(0xffffffffu, t, 2));
                mx[mf][h] = t;
            }
        if ((lane & 3) == 0) {
            #pragma unroll
            for (int mf = 0; mf < 2; mf++)
                #pragma unroll
                for (int h = 0; h < 2; h++)
                    redA[warpN * 128 + warpM * 32 + mf * 16 + h * 8 + rq] = mx[mf][h];
        }
        __syncthreads();

        float mnew[2][2], scale[2][2], rsum[2][2];
        #pragma unroll
        for (int mf = 0; mf < 2; mf++)
            #pragma unroll
            for (int h = 0; h < 2; h++) {
                int r = warpM * 32 + mf * 16 + h * 8 + rq;
                float v = m[mf][h];
                #pragma unroll
                for (int w = 0; w < 4; w++) v = fmaxf(v, redA[w * 128 + r]);
                mnew[mf][h] = v;
                rsum[mf][h] = 0.f;
            }

        #pragma unroll
        for (int mf = 0; mf < 2; mf++)
            #pragma unroll
            for (int nf = 0; nf < 2; nf++)
                #pragma unroll
                for (int h = 0; h < 2; h++) {
                    float p0 = ex2f(aq[mf][nf][h * 2]     - mnew[mf][h]);
                    float p1 = ex2f(aq[mf][nf][h * 2 + 1] - mnew[mf][h]);
                    rsum[mf][h] += p0 + p1;
                    __nv_bfloat16 h0 = __float2bfloat16(p0);
                    __nv_bfloat16 h1 = __float2bfloat16(p1);
                    __nv_bfloat16 l0 = __float2bfloat16(p0 - __bfloat162float(h0));
                    __nv_bfloat16 l1 = __float2bfloat16(p1 - __bfloat162float(h1));
                    int row = warpM * 32 + mf * 16 + h * 8 + rq;
                    int col = warpN * 16 + nf * 8 + cq2;
                    __nv_bfloat162 hv; hv.x = h0; hv.y = h1;
                    __nv_bfloat162 lv; lv.x = l0; lv.y = l1;
                    *(__nv_bfloat162*)(sb + OFF_SPH + row * 72 + col) = hv;
                    *(__nv_bfloat162*)(sb + OFF_SPL + row * 72 + col) = lv;
                }
        #pragma unroll
        for (int mf = 0; mf < 2; mf++)
            #pragma unroll
            for (int h = 0; h < 2; h++) {
                float t = rsum[mf][h];
                t += __shfl_xor_sync(0xffffffffu, t, 1);
                t += __shfl_xor_sync(0xffffffffu, t, 2);
                rsum[mf][h] = t;
                scale[mf][h] = ex2f(m[mf][h] - mnew[mf][h]);
                m[mf][h] = mnew[mf][h];
            }
        if ((lane & 3) == 0) {
            #pragma unroll
            for (int mf = 0; mf < 2; mf++)
                #pragma unroll
                for (int h = 0; h < 2; h++)
                    redB[warpN * 128 + warpM * 32 + mf * 16 + h * 8 + rq] = rsum[mf][h];
        }
        if (kt + 1 < 16) { CP_WAIT(1); }
        else             { CP_WAIT(0); }
        __syncthreads();

        #pragma unroll
        for (int mf = 0; mf < 2; mf++)
            #pragma unroll
            for (int h = 0; h < 2; h++) {
                int r = warpM * 32 + mf * 16 + h * 8 + rq;
                float s = 0.f;
                #pragma unroll
                for (int w = 0; w < 4; w++) s += redB[w * 128 + r];
                l[mf][h] = l[mf][h] * scale[mf][h] + s;
            }
        #pragma unroll
        for (int mf = 0; mf < 2; mf++)
            #pragma unroll
            for (int nf = 0; nf < 8; nf++) {
                acc[mf][nf][0] *= scale[mf][0];
                acc[mf][nf][1] *= scale[mf][0];
                acc[mf][nf][2] *= scale[mf][1];
                acc[mf][nf][3] *= scale[mf][1];
            }

        #pragma unroll
        for (int k0 = 0; k0 < 64; k0 += 16) {
            uint32_t ph0[4], ph1[4], pl0[4], pl1[4];
            uint32_t colA = k0 + (lane >> 4) * 8;
            LDSM_X4(ph0[0], ph0[1], ph0[2], ph0[3], sb32 + (OFF_SPH + (rowA) * 72 + colA) * 2);
            LDSM_X4(ph1[0], ph1[1], ph1[2], ph1[3], sb32 + (OFF_SPH + (rowA + 16) * 72 + colA) * 2);
            LDSM_X4(pl0[0], pl0[1], pl0[2], pl0[3], sb32 + (OFF_SPL + (rowA) * 72 + colA) * 2);
            LDSM_X4(pl1[0], pl1[1], pl1[2], pl1[3], sb32 + (OFF_SPL + (rowA + 16) * 72 + colA) * 2);
            int g = lane >> 3, rr = lane & 7;
            #pragma unroll
            for (int j2 = 0; j2 < 4; j2++) {
                uint32_t gh[4], gl[4];
                uint32_t brow = (warpN * 64 + j2 * 16 + (g & 2) * 4 + rr) * 72 + k0 + (g & 1) * 8;
                LDSM_X4(gh[0], gh[1], gh[2], gh[3], sb32 + (OFF_GH + brow) * 2);
                LDSM_X4(gl[0], gl[1], gl[2], gl[3], sb32 + (OFF_GL + brow) * 2);
                MMA16816(acc[0][j2 * 2 + 0], ph0, gh[0], gh[1]);
                MMA16816(acc[0][j2 * 2 + 1], ph0, gh[2], gh[3]);
                MMA16816(acc[1][j2 * 2 + 0], ph1, gh[0], gh[1]);
                MMA16816(acc[1][j2 * 2 + 1], ph1, gh[2], gh[3]);
                MMA16816(acc[0][j2 * 2 + 0], pl0, gh[0], gh[1]);
                MMA16816(acc[0][j2 * 2 + 1], pl0, gh[2], gh[3]);
                MMA16816(acc[1][j2 * 2 + 0], pl1, gh[0], gh[1]);
                MMA16816(acc[1][j2 * 2 + 1], pl1, gh[2], gh[3]);
                MMA16816(acc[0][j2 * 2 + 0], ph0, gl[0], gl[1]);
                MMA16816(acc[0][j2 * 2 + 1], ph0, gl[2], gl[3]);
                MMA16816(acc[1][j2 * 2 + 0], ph1, gl[0], gl[1]);
                MMA16816(acc[1][j2 * 2 + 1], ph1, gl[2], gl[3]);
            }
        }
    }

    // epilogue: tmp = acc / l -> fp16 hi/lo (feeds fp16 Wo GEMM)
    #pragma unroll
    for (int mf = 0; mf < 2; mf++)
        #pragma unroll
        for (int h = 0; h < 2; h++) {
            float inv = 1.f / l[mf][h];
            int row = qbase + warpM * 32 + mf * 16 + h * 8 + rq;
            #pragma unroll
            for (int nf = 0; nf < 8; nf++) {
                int col = warpN * 64 + nf * 8 + cq2;
                float v0 = acc[mf][nf][h * 2]     * inv;
                float v1 = acc[mf][nf][h * 2 + 1] * inv;
                __half h0 = __float2half(v0);
                __half h1 = __float2half(v1);
                __half l0 = __float2half(v0 - __half2float(h0));
                __half l1 = __float2half(v1 - __half2float(h1));
                __half2 hv; hv.x = h0; hv.y = h1;
                __half2 lv; lv.x = l0; lv.y = l1;
                *(__half2*)(thi + (size_t)row * V_DIM + col) = hv;
                *(__half2*)(tlo + (size_t)row * V_DIM + col) = lv;
            }
        }
}

// ---------------- launch ----------------
extern "C" void kernel_launch(void* const* d_in, const int* in_sizes, int n_in,
                              void* d_out, int out_size)
{
    const float* x     = (const float*)d_in[0];
    const float* Wt    = (const float*)d_in[1];
    const float* Wp    = (const float*)d_in[2];
    const float* Wg    = (const float*)d_in[3];
    const float* Wo    = (const float*)d_in[4];
    const float* gamma = (const float*)d_in[5];
    float* out = (float*)d_out;

    float *proj, *gP;
    __half *xhi, *xlo, *thi, *tlo, *Bph, *Bpl, *Boh, *Bol;
    __nv_bfloat16 *fhi, *flo, *gth, *gtl;
    cudaGetSymbolAddress((void**)&proj, g_proj);
    cudaGetSymbolAddress((void**)&gP,   g_gP);
    cudaGetSymbolAddress((void**)&xhi,  g_xhi);
    cudaGetSymbolAddress((void**)&xlo,  g_xlo);
    cudaGetSymbolAddress((void**)&thi,  g_thi);
    cudaGetSymbolAddress((void**)&tlo,  g_tlo);
    cudaGetSymbolAddress((void**)&Bph,  g_Bp_hi);
    cudaGetSymbolAddress((void**)&Bpl,  g_Bp_lo);
    cudaGetSymbolAddress((void**)&Boh,  g_Bo_hi);
    cudaGetSymbolAddress((void**)&Bol,  g_Bo_lo);
    cudaGetSymbolAddress((void**)&fhi,  g_fhi);
    cudaGetSymbolAddress((void**)&flo,  g_flo);
    cudaGetSymbolAddress((void**)&gth,  g_gth);
    cudaGetSymbolAddress((void**)&gtl,  g_gtl);

    cudaFuncSetAttribute(gemm_mma<512>, cudaFuncAttributeMaxDynamicSharedMemorySize, GEMM_SMEM_BYTES);
    cudaFuncSetAttribute(gemm_mma<256>, cudaFuncAttributeMaxDynamicSharedMemorySize, GEMM_SMEM_BYTES);
    cudaFuncSetAttribute(attn_k, cudaFuncAttributeMaxDynamicSharedMemorySize, ATTN_SMEM_BYTES);

    convert_x_k<<<(M_ROWS * C_IN / 8 + 255) / 256, 256>>>(x, xhi, xlo);
    pack_proj_k<<<(NPROJ * C_IN + 255) / 256, 256>>>(Wt, Wp, Wg, Bph, Bpl);
    pack_wo_k<<<(C_IN * V_DIM + 255) / 256, 256>>>(Wo, Boh, Bol);
    gemm_mma<512><<<dim3(NPROJ / 128, M_ROWS / 128), 256, GEMM_SMEM_BYTES>>>(
        xhi, xlo, Bph, Bpl, proj, NPROJ, nullptr, nullptr);
    {
        int total = BATCH * SEQ_K * (D_DIM / 4) + BATCH * SEQ_K * (V_DIM / 4);
        pool_k<<<(total + 255) / 256, 256>>>(proj, fhi, flo, gP);
    }
    transT_g_k<<<dim3(V_DIM / 32, SEQ_K / 32, BATCH), 256>>>(gP, gth, gtl);
    attn_k<<<dim3(SEQ_Q / 128, BATCH), 512, ATTN_SMEM_BYTES>>>(
        proj, fhi, flo, gth, gtl, thi, tlo);
    gemm_mma<256><<<dim3(C_IN / 128, M_ROWS / 128), 256, GEMM_SMEM_BYTES>>>(
        thi, tlo, Boh, Bol, out, C_IN, x, gamma);
}